// round 1
// baseline (speedup 1.0000x reference)
#include <cuda_runtime.h>

#define G       8
#define N0      16384
#define CC      128
#define LL      3
#define HH      256
#define EPS_FA  0.1f
#define EMAX    1048576

// Node counts: L0 131072, L1 65536, L2 32768
#define NMAX    131072

// ---------------- scratch (device globals; no allocations) ----------------
__device__ float g_acc [NMAX * CC];          // accumulator / h for current layer (64MB)
__device__ float g_cur [65536 * CC];         // cur features from layer 1 on (32MB)
__device__ float g_origA[65536 * CC];        // orig after pool 0 (32MB)
__device__ float g_origB[32768 * CC];        // orig after pool 1 (16MB)
__device__ int   g_srcA[EMAX], g_dstA[EMAX]; // compacted edges after pool 0
__device__ int   g_srcB[EMAX], g_dstB[EMAX]; // compacted edges after pool 1
__device__ float g_al[NMAX], g_ar[NMAX], g_dinv[NMAX];
__device__ int   g_deg[NMAX], g_score[NMAX], g_nmap[NMAX];
__device__ int   g_perm[65536];
__device__ float g_pool[LL * G * CC];
__device__ int   g_cnt[2];

// ---------------- kernels ----------------

__global__ void k_init()
{
    if (threadIdx.x == 0) { g_cnt[0] = 0; g_cnt[1] = 0; }
}

// out-degree (score) over src, in-degree (deg) over dst
__global__ void k_degree(const int* __restrict__ src, const int* __restrict__ dst,
                         int ecnt_fixed, const int* __restrict__ ecnt_ptr)
{
    int E = ecnt_ptr ? *ecnt_ptr : ecnt_fixed;
    for (int e = blockIdx.x * blockDim.x + threadIdx.x; e < E;
         e += gridDim.x * blockDim.x) {
        atomicAdd(&g_deg[dst[e]], 1);
        atomicAdd(&g_score[src[e]], 1);
    }
}

// per node: al, ar dots; dinv; acc = self-loop message + EPS*orig
__global__ void k_nodeprep(const float* __restrict__ cur, const float* __restrict__ orig,
                           const float* __restrict__ attl, const float* __restrict__ attr,
                           int n)
{
    int warp = (blockIdx.x * blockDim.x + threadIdx.x) >> 5;
    int lane = threadIdx.x & 31;
    if (warp >= n) return;
    const float4* c4 = (const float4*)(cur  + (size_t)warp * CC);
    const float4* o4 = (const float4*)(orig + (size_t)warp * CC);
    float4 cv = c4[lane];
    float4 lv = ((const float4*)attl)[lane];
    float4 rv = ((const float4*)attr)[lane];
    float al = cv.x*lv.x + cv.y*lv.y + cv.z*lv.z + cv.w*lv.w;
    float ar = cv.x*rv.x + cv.y*rv.y + cv.z*rv.z + cv.w*rv.w;
#pragma unroll
    for (int o = 16; o; o >>= 1) {
        al += __shfl_xor_sync(0xffffffffu, al, o);
        ar += __shfl_xor_sync(0xffffffffu, ar, o);
    }
    float dinv = rsqrtf((float)g_deg[warp] + 1.0f);
    if (lane == 0) { g_al[warp] = al; g_ar[warp] = ar; g_dinv[warp] = dinv; }
    float coef = dinv * dinv * tanhf(al + ar);
    float4 ov = o4[lane];
    float4 a;
    a.x = coef*cv.x + EPS_FA*ov.x;
    a.y = coef*cv.y + EPS_FA*ov.y;
    a.z = coef*cv.z + EPS_FA*ov.z;
    a.w = coef*cv.w + EPS_FA*ov.w;
    ((float4*)(g_acc + (size_t)warp * CC))[lane] = a;
}

// warp per edge: acc[dst] += dinv[s]*dinv[d]*tanh(al[d]+ar[s]) * cur[src]
__global__ void k_edgemsg(const int* __restrict__ src, const int* __restrict__ dst,
                          int ecnt_fixed, const int* __restrict__ ecnt_ptr,
                          const float* __restrict__ cur)
{
    int E = ecnt_ptr ? *ecnt_ptr : ecnt_fixed;
    int lane   = threadIdx.x & 31;
    int warp   = (blockIdx.x * blockDim.x + threadIdx.x) >> 5;
    int nwarps = (gridDim.x * blockDim.x) >> 5;
    for (int e = warp; e < E; e += nwarps) {
        int s = src[e], d = dst[e];
        float coef = g_dinv[s] * g_dinv[d] * tanhf(g_al[d] + g_ar[s]);
        float4 v = ((const float4*)(cur + (size_t)s * CC))[lane];
        float* p = g_acc + (size_t)d * CC + lane * 4;
        asm volatile("red.global.add.v4.f32 [%0], {%1,%2,%3,%4};"
                     :: "l"(p), "f"(coef*v.x), "f"(coef*v.y),
                        "f"(coef*v.z), "f"(coef*v.w) : "memory");
    }
}

// relu in place + per-graph per-channel max pool (block-local max, then 1 atomic)
__global__ void k_finalize(int npg, int layer)
{
    int c = threadIdx.x;                  // 128 channels
    int base = blockIdx.x * 64;           // 64 nodes per block; npg multiple of 64
    int g = base / npg;
    float mx = 0.0f;
#pragma unroll 4
    for (int i = 0; i < 64; i++) {
        size_t idx = (size_t)(base + i) * CC + c;
        float v = g_acc[idx];
        v = fmaxf(v, 0.0f);
        g_acc[idx] = v;
        mx = fmaxf(mx, v);
    }
    atomicMax((unsigned*)&g_pool[layer * G * CC + g * CC + c], __float_as_uint(mx));
}

// exact stable top-k per graph: bitonic sort of (score desc, index asc) keys
extern __shared__ unsigned s_keys[];
__global__ void k_sort(int npg, int kk)
{
    int g = blockIdx.x;
    int tid = threadIdx.x, bd = blockDim.x;
    unsigned mask = (unsigned)npg - 1u;
    for (int li = tid; li < npg; li += bd) {
        unsigned sc = (unsigned)g_score[g * npg + li];
        if (sc > 0x3FFFFu) sc = 0x3FFFFu;
        s_keys[li] = (sc << 14) | (unsigned)(npg - 1 - li);
    }
    __syncthreads();
    for (unsigned size = 2; size <= (unsigned)npg; size <<= 1) {
        for (unsigned stride = size >> 1; stride > 0; stride >>= 1) {
            for (int i = tid; i < npg / 2; i += bd) {
                unsigned pos = 2u * i - ((unsigned)i & (stride - 1u));
                bool desc = ((pos & size) == 0u);  // final full pass: descending
                unsigned a = s_keys[pos], b = s_keys[pos + stride];
                if ((a < b) == desc) { s_keys[pos] = b; s_keys[pos + stride] = a; }
            }
            __syncthreads();
        }
    }
    for (int li = tid; li < npg; li += bd) g_nmap[g * npg + li] = -1;
    __syncthreads();
    for (int j = tid; j < kk; j += bd) {
        unsigned key = s_keys[j];
        int li  = npg - 1 - (int)(key & mask);
        int old = g * npg + li;
        int neu = g * kk + j;
        g_perm[neu] = old;
        g_nmap[old] = neu;
    }
}

// gather kept nodes: cur_out[j]=h[perm[j]], orig_out[j]=orig[perm[j]]
__global__ void k_gather(const float* __restrict__ h, const float* __restrict__ orig_old,
                         float* __restrict__ cur_out, float* __restrict__ orig_out, int cnt)
{
    int warp = (blockIdx.x * blockDim.x + threadIdx.x) >> 5;
    int lane = threadIdx.x & 31;
    if (warp >= cnt) return;
    int old = g_perm[warp];
    ((float4*)(cur_out  + (size_t)warp * CC))[lane] =
        ((const float4*)(h        + (size_t)old * CC))[lane];
    ((float4*)(orig_out + (size_t)warp * CC))[lane] =
        ((const float4*)(orig_old + (size_t)old * CC))[lane];
}

// keep edges with both endpoints surviving; remap; warp-aggregated append
__global__ void k_compact(const int* __restrict__ src, const int* __restrict__ dst,
                          int ecnt_fixed, const int* __restrict__ ecnt_ptr,
                          int* __restrict__ osrc, int* __restrict__ odst,
                          int* __restrict__ cnt)
{
    int E = ecnt_ptr ? *ecnt_ptr : ecnt_fixed;
    int lane   = threadIdx.x & 31;
    int warp   = (blockIdx.x * blockDim.x + threadIdx.x) >> 5;
    int nwarps = (gridDim.x * blockDim.x) >> 5;
    for (int base = warp * 32; base < E; base += nwarps * 32) {
        int e = base + lane;
        bool keep = false; int ns = 0, nd = 0;
        if (e < E) {
            ns = g_nmap[src[e]];
            nd = g_nmap[dst[e]];
            keep = (ns >= 0) && (nd >= 0);
        }
        unsigned bal = __ballot_sync(0xffffffffu, keep);
        int tot = __popc(bal);
        int pos = 0;
        if (lane == 0 && tot) pos = atomicAdd(cnt, tot);
        pos = __shfl_sync(0xffffffffu, pos, 0);
        if (keep) {
            int off = __popc(bal & ((1u << lane) - 1u));
            osrc[pos + off] = ns;
            odst[pos + off] = nd;
        }
    }
}

// GRU (h0=0) + final linears + root residual; one block per graph
__global__ void k_head(const float* __restrict__ w_ih, const float* __restrict__ b_ih,
                       const float* __restrict__ b_hh,
                       const float* __restrict__ w_fin, const float* __restrict__ b_fin,
                       const float* __restrict__ w_root, const float* __restrict__ b_root,
                       const float* __restrict__ root, const float* __restrict__ alpha_p,
                       float* __restrict__ out)
{
    __shared__ float fused[LL * CC];
    __shared__ float hgru[HH];
    __shared__ float rootv[CC];
    int g = blockIdx.x, t = threadIdx.x;  // 256 threads
    for (int i = t; i < LL * CC; i += 256) {
        int layer = i >> 7, c = i & 127;
        fused[i] = g_pool[layer * G * CC + g * CC + c];
    }
    if (t < CC) rootv[t] = root[g * CC + t];
    __syncthreads();

    float gr = b_ih[t], gz = b_ih[HH + t], gn = b_ih[2 * HH + t];
    const float* wr = w_ih + (size_t)t            * (LL * CC);
    const float* wz = w_ih + (size_t)(HH + t)     * (LL * CC);
    const float* wn = w_ih + (size_t)(2 * HH + t) * (LL * CC);
    for (int j = 0; j < LL * CC; j++) {
        float f = fused[j];
        gr += wr[j] * f; gz += wz[j] * f; gn += wn[j] * f;
    }
    float r  = 1.0f / (1.0f + expf(-(gr + b_hh[t])));
    float z  = 1.0f / (1.0f + expf(-(gz + b_hh[HH + t])));
    float nc = tanhf(gn + r * b_hh[2 * HH + t]);
    hgru[t] = (1.0f - z) * nc;
    __syncthreads();

    if (t < CC) {
        float acc = b_fin[t];
        const float* wf = w_fin + (size_t)t * HH;
        for (int j = 0; j < HH; j++) acc += wf[j] * hgru[j];
        float re = b_root[t];
        const float* wo = w_root + (size_t)t * CC;
        for (int j = 0; j < CC; j++) re += wo[j] * rootv[j];
        float a = *alpha_p;
        out[g * CC + t] = a * acc + (1.0f - a) * re;
    }
}

// ---------------- launch ----------------

extern "C" void kernel_launch(void* const* d_in, const int* in_sizes, int n_in,
                              void* d_out, int out_size)
{
    const float* x      = (const float*)d_in[0];
    const int*   ei     = (const int*)  d_in[1];
    const float* root   = (const float*)d_in[3];
    const float* att_l  = (const float*)d_in[4];
    const float* att_r  = (const float*)d_in[5];
    const float* w_ih   = (const float*)d_in[6];
    const float* b_ih   = (const float*)d_in[8];
    const float* b_hh   = (const float*)d_in[9];
    const float* w_fin  = (const float*)d_in[10];
    const float* b_fin  = (const float*)d_in[11];
    const float* w_root = (const float*)d_in[12];
    const float* b_root = (const float*)d_in[13];
    const float* alpha  = (const float*)d_in[14];
    float* out = (float*)d_out;

    int E = in_sizes[1] / 2;
    const int* src0 = ei;
    const int* dst0 = ei + E;

    // symbol addresses for memset / parametrized buffers
    float *acc, *cur, *origA, *origB, *pool;
    int *srcA, *dstA, *srcB, *dstB, *deg, *score, *cnt;
    cudaGetSymbolAddress((void**)&acc,   g_acc);
    cudaGetSymbolAddress((void**)&cur,   g_cur);
    cudaGetSymbolAddress((void**)&origA, g_origA);
    cudaGetSymbolAddress((void**)&origB, g_origB);
    cudaGetSymbolAddress((void**)&pool,  g_pool);
    cudaGetSymbolAddress((void**)&srcA,  g_srcA);
    cudaGetSymbolAddress((void**)&dstA,  g_dstA);
    cudaGetSymbolAddress((void**)&srcB,  g_srcB);
    cudaGetSymbolAddress((void**)&dstB,  g_dstB);
    cudaGetSymbolAddress((void**)&deg,   g_deg);
    cudaGetSymbolAddress((void**)&score, g_score);
    cudaGetSymbolAddress((void**)&cnt,   g_cnt);

    cudaFuncSetAttribute(k_sort, cudaFuncAttributeMaxDynamicSharedMemorySize, 64 * 1024);

    k_init<<<1, 32>>>();
    cudaMemsetAsync(pool, 0, LL * G * CC * sizeof(float));

    // ---------- Layer 0 (n = 131072, npg = 16384) ----------
    cudaMemsetAsync(deg,   0, NMAX * sizeof(int));
    cudaMemsetAsync(score, 0, NMAX * sizeof(int));
    k_degree  <<<1024, 256>>>(src0, dst0, E, nullptr);
    k_nodeprep<<<131072 / 8, 256>>>(x, x, att_l, att_r, 131072);
    k_edgemsg <<<2048, 256>>>(src0, dst0, E, nullptr, x);
    k_finalize<<<131072 / 64, 128>>>(16384, 0);
    k_sort    <<<8, 1024, 16384 * 4>>>(16384, 8192);
    k_gather  <<<65536 / 8, 256>>>(acc, x, cur, origA, 65536);
    k_compact <<<1024, 256>>>(src0, dst0, E, nullptr, srcA, dstA, cnt + 0);

    // ---------- Layer 1 (n = 65536, npg = 8192) ----------
    cudaMemsetAsync(deg,   0, 65536 * sizeof(int));
    cudaMemsetAsync(score, 0, 65536 * sizeof(int));
    k_degree  <<<1024, 256>>>(srcA, dstA, 0, cnt + 0);
    k_nodeprep<<<65536 / 8, 256>>>(cur, origA, att_l + CC, att_r + CC, 65536);
    k_edgemsg <<<2048, 256>>>(srcA, dstA, 0, cnt + 0, cur);
    k_finalize<<<65536 / 64, 128>>>(8192, 1);
    k_sort    <<<8, 1024, 8192 * 4>>>(8192, 4096);
    k_gather  <<<32768 / 8, 256>>>(acc, origA, cur, origB, 32768);
    k_compact <<<1024, 256>>>(srcA, dstA, 0, cnt + 0, srcB, dstB, cnt + 1);

    // ---------- Layer 2 (n = 32768, npg = 4096) ----------
    cudaMemsetAsync(deg,   0, 32768 * sizeof(int));
    cudaMemsetAsync(score, 0, 32768 * sizeof(int));
    k_degree  <<<1024, 256>>>(srcB, dstB, 0, cnt + 1);
    k_nodeprep<<<32768 / 8, 256>>>(cur, origB, att_l + 2 * CC, att_r + 2 * CC, 32768);
    k_edgemsg <<<2048, 256>>>(srcB, dstB, 0, cnt + 1, cur);
    k_finalize<<<32768 / 64, 128>>>(4096, 2);

    // ---------- Head ----------
    k_head<<<G, 256>>>(w_ih, b_ih, b_hh, w_fin, b_fin, w_root, b_root,
                       root, alpha, out);
}

// round 2
// speedup vs baseline: 1.1361x; 1.1361x over previous
#include <cuda_runtime.h>

#define G       8
#define N0      16384
#define CC      128
#define LL      3
#define HH      256
#define EPS_FA  0.1f
#define EMAX    1048576
#define NMAX    131072

// ---------------- scratch (device globals; no allocations) ----------------
__device__ float g_acc [NMAX * CC];          // h output for current layer (64MB)
__device__ float g_cur [65536 * CC];         // cur features from layer 1 on (32MB)
__device__ int   g_srcA[EMAX], g_dstA[EMAX]; // compacted edges after pool 0
__device__ int   g_srcB[EMAX], g_dstB[EMAX]; // compacted edges after pool 1
__device__ int   g_csr [EMAX];               // CSR src lists (by dst)
__device__ float g_al[NMAX], g_ar[NMAX], g_dinv[NMAX];
__device__ int   g_deg[NMAX], g_score[NMAX], g_fill[NMAX];
__device__ int   g_offs[NMAX], g_bsum[256];
__device__ int   g_nmap[NMAX];
__device__ int   g_perm[65536];
__device__ int   g_oidxA[65536], g_oidxB[32768];
__device__ float g_pool[LL * G * CC];
__device__ int   g_cnt[2];

// ---------------- kernels ----------------

__global__ void k_zero(int n, int first)
{
    int i = blockIdx.x * blockDim.x + threadIdx.x;
    if (i < n) { g_deg[i] = 0; g_score[i] = 0; g_fill[i] = 0; }
    if (first) {
        if (i < LL * G * CC) g_pool[i] = 0.0f;
        if (i < 2) g_cnt[i] = 0;
    }
}

// out-degree (score) over src, in-degree (deg) over dst
__global__ void k_degree(const int* __restrict__ src, const int* __restrict__ dst,
                         int ecnt_fixed, const int* __restrict__ ecnt_ptr)
{
    int E = ecnt_ptr ? *ecnt_ptr : ecnt_fixed;
    for (int e = blockIdx.x * blockDim.x + threadIdx.x; e < E;
         e += gridDim.x * blockDim.x) {
        atomicAdd(&g_deg[dst[e]], 1);
        atomicAdd(&g_score[src[e]], 1);
    }
}

// two-level exclusive scan of deg -> (g_offs within-block exclusive, g_bsum block offsets)
__global__ void k_scan1()
{
    __shared__ int sh[1024];
    int tid = threadIdx.x;
    int i = blockIdx.x * 1024 + tid;
    int v = g_deg[i];
    sh[tid] = v;
    __syncthreads();
    int acc = v;
#pragma unroll
    for (int off = 1; off < 1024; off <<= 1) {
        int add = (tid >= off) ? sh[tid - off] : 0;
        __syncthreads();
        acc += add;
        sh[tid] = acc;
        __syncthreads();
    }
    g_offs[i] = acc - v;                    // exclusive within block
    if (tid == 1023) g_bsum[blockIdx.x] = acc;
}

__global__ void k_scan2(int nb)
{
    __shared__ int sh[128];
    int tid = threadIdx.x;
    int v = (tid < nb) ? g_bsum[tid] : 0;
    sh[tid] = v;
    __syncthreads();
    int acc = v;
#pragma unroll
    for (int off = 1; off < 128; off <<= 1) {
        int add = (tid >= off) ? sh[tid - off] : 0;
        __syncthreads();
        acc += add;
        sh[tid] = acc;
        __syncthreads();
    }
    if (tid < nb) g_bsum[tid] = acc - v;    // exclusive over blocks
}

// scatter edges into CSR-by-dst (src stored; order within dst arbitrary)
__global__ void k_scatter(const int* __restrict__ src, const int* __restrict__ dst,
                          int ecnt_fixed, const int* __restrict__ ecnt_ptr)
{
    int E = ecnt_ptr ? *ecnt_ptr : ecnt_fixed;
    for (int e = blockIdx.x * blockDim.x + threadIdx.x; e < E;
         e += gridDim.x * blockDim.x) {
        int d = dst[e];
        int p = atomicAdd(&g_fill[d], 1);
        g_csr[g_offs[d] + g_bsum[d >> 10] + p] = src[e];
    }
}

// per node: al, ar dots and dinv (no feature write)
__global__ void k_nodeprep(const float* __restrict__ cur,
                           const float* __restrict__ attl, const float* __restrict__ attr,
                           int n)
{
    int warp = (blockIdx.x * blockDim.x + threadIdx.x) >> 5;
    int lane = threadIdx.x & 31;
    if (warp >= n) return;
    float4 cv = __ldg((const float4*)(cur + (size_t)warp * CC) + lane);
    float4 lv = ((const float4*)attl)[lane];
    float4 rv = ((const float4*)attr)[lane];
    float al = cv.x*lv.x + cv.y*lv.y + cv.z*lv.z + cv.w*lv.w;
    float ar = cv.x*rv.x + cv.y*rv.y + cv.z*rv.z + cv.w*rv.w;
#pragma unroll
    for (int o = 16; o; o >>= 1) {
        al += __shfl_xor_sync(0xffffffffu, al, o);
        ar += __shfl_xor_sync(0xffffffffu, ar, o);
    }
    if (lane == 0) {
        g_al[warp]   = al;
        g_ar[warp]   = ar;
        g_dinv[warp] = rsqrtf((float)g_deg[warp] + 1.0f);
    }
}

// warp per dst node: register-accumulate in-edges (CSR), self loop, EPS term,
// relu, write h, fused per-graph per-channel max pool.
__global__ void k_agg(const float* __restrict__ cur, const float* __restrict__ x,
                      const int* __restrict__ oidx, int log2npg, int layer)
{
    __shared__ unsigned smax[128];
    int tid  = threadIdx.x;
    int lane = tid & 31;
    if (tid < 128) smax[tid] = 0;
    __syncthreads();

    int d = (blockIdx.x * blockDim.x + tid) >> 5;   // grid sized exactly: no bounds check
    int start = g_offs[d] + g_bsum[d >> 10];
    int cnt   = g_deg[d];
    float dind = g_dinv[d];
    float ald  = g_al[d];

    float4 a = {0.f, 0.f, 0.f, 0.f};
    for (int base = 0; base < cnt; base += 32) {
        int j = base + lane;
        int s = -1; float coef = 0.f;
        if (j < cnt) {
            s = g_csr[start + j];
            coef = g_dinv[s] * dind * tanhf(ald + g_ar[s]);
        }
        int m = min(32, cnt - base);
        for (int t = 0; t < m; t++) {
            int   ss = __shfl_sync(0xffffffffu, s, t);
            float cc = __shfl_sync(0xffffffffu, coef, t);
            float4 v = __ldg((const float4*)(cur + (size_t)ss * CC) + lane);
            a.x += cc * v.x; a.y += cc * v.y; a.z += cc * v.z; a.w += cc * v.w;
        }
    }

    // self-loop + EPS * orig, relu
    float4 cv = __ldg((const float4*)(cur + (size_t)d * CC) + lane);
    int oi = oidx ? oidx[d] : d;
    float4 ov = __ldg((const float4*)(x + (size_t)oi * CC) + lane);
    float c0 = dind * dind * tanhf(ald + g_ar[d]);
    a.x = fmaxf(c0*cv.x + EPS_FA*ov.x + a.x, 0.f);
    a.y = fmaxf(c0*cv.y + EPS_FA*ov.y + a.y, 0.f);
    a.z = fmaxf(c0*cv.z + EPS_FA*ov.z + a.z, 0.f);
    a.w = fmaxf(c0*cv.w + EPS_FA*ov.w + a.w, 0.f);
    ((float4*)g_acc)[(size_t)d * 32 + lane] = a;

    // fused pool: block-shared max then one global atomic per channel
    atomicMax(&smax[lane*4 + 0], __float_as_uint(a.x));
    atomicMax(&smax[lane*4 + 1], __float_as_uint(a.y));
    atomicMax(&smax[lane*4 + 2], __float_as_uint(a.z));
    atomicMax(&smax[lane*4 + 3], __float_as_uint(a.w));
    __syncthreads();
    if (tid < 128) {
        int g = (int)((blockIdx.x * (blockDim.x >> 5)) >> log2npg);
        atomicMax((unsigned*)&g_pool[(layer * G + g) * CC + tid], smax[tid]);
    }
}

// exact stable top-k per graph: bitonic sort of (score desc, index asc) keys
extern __shared__ unsigned s_keys[];
__global__ void k_sort(int npg, int kk)
{
    int g = blockIdx.x;
    int tid = threadIdx.x, bd = blockDim.x;
    unsigned mask = (unsigned)npg - 1u;
    for (int li = tid; li < npg; li += bd) {
        unsigned sc = (unsigned)g_score[g * npg + li];
        if (sc > 0x3FFFFu) sc = 0x3FFFFu;
        s_keys[li] = (sc << 14) | (unsigned)(npg - 1 - li);
    }
    __syncthreads();
    for (unsigned size = 2; size <= (unsigned)npg; size <<= 1) {
        for (unsigned stride = size >> 1; stride > 0; stride >>= 1) {
            for (int i = tid; i < npg / 2; i += bd) {
                unsigned pos = 2u * i - ((unsigned)i & (stride - 1u));
                bool desc = ((pos & size) == 0u);
                unsigned a = s_keys[pos], b = s_keys[pos + stride];
                if ((a < b) == desc) { s_keys[pos] = b; s_keys[pos + stride] = a; }
            }
            __syncthreads();
        }
    }
    for (int li = tid; li < npg; li += bd) g_nmap[g * npg + li] = -1;
    __syncthreads();
    for (int j = tid; j < kk; j += bd) {
        unsigned key = s_keys[j];
        int li  = npg - 1 - (int)(key & mask);
        int old = g * npg + li;
        int neu = g * kk + j;
        g_perm[neu] = old;
        g_nmap[old] = neu;
    }
}

// gather kept nodes' features (h already relu'd) + compose orig indices
__global__ void k_gather(const float* __restrict__ h, float* __restrict__ cur_out,
                         const int* __restrict__ oidx_old, int* __restrict__ oidx_new,
                         int cnt)
{
    int warp = (blockIdx.x * blockDim.x + threadIdx.x) >> 5;
    int lane = threadIdx.x & 31;
    if (warp >= cnt) return;
    int old = g_perm[warp];
    ((float4*)(cur_out + (size_t)warp * CC))[lane] =
        __ldg((const float4*)(h + (size_t)old * CC) + lane);
    if (lane == 0) oidx_new[warp] = oidx_old ? oidx_old[old] : old;
}

// keep edges with both endpoints surviving; remap; warp-aggregated append
__global__ void k_compact(const int* __restrict__ src, const int* __restrict__ dst,
                          int ecnt_fixed, const int* __restrict__ ecnt_ptr,
                          int* __restrict__ osrc, int* __restrict__ odst,
                          int* __restrict__ cnt)
{
    int E = ecnt_ptr ? *ecnt_ptr : ecnt_fixed;
    int lane   = threadIdx.x & 31;
    int warp   = (blockIdx.x * blockDim.x + threadIdx.x) >> 5;
    int nwarps = (gridDim.x * blockDim.x) >> 5;
    for (int base = warp * 32; base < E; base += nwarps * 32) {
        int e = base + lane;
        bool keep = false; int ns = 0, nd = 0;
        if (e < E) {
            ns = g_nmap[src[e]];
            nd = g_nmap[dst[e]];
            keep = (ns >= 0) && (nd >= 0);
        }
        unsigned bal = __ballot_sync(0xffffffffu, keep);
        int tot = __popc(bal);
        int pos = 0;
        if (lane == 0 && tot) pos = atomicAdd(cnt, tot);
        pos = __shfl_sync(0xffffffffu, pos, 0);
        if (keep) {
            int off = __popc(bal & ((1u << lane) - 1u));
            osrc[pos + off] = ns;
            odst[pos + off] = nd;
        }
    }
}

// GRU (h0=0) + final linears + root residual; one block per graph
__global__ void k_head(const float* __restrict__ w_ih, const float* __restrict__ b_ih,
                       const float* __restrict__ b_hh,
                       const float* __restrict__ w_fin, const float* __restrict__ b_fin,
                       const float* __restrict__ w_root, const float* __restrict__ b_root,
                       const float* __restrict__ root, const float* __restrict__ alpha_p,
                       float* __restrict__ out)
{
    __shared__ float fused[LL * CC];
    __shared__ float hgru[HH];
    __shared__ float rootv[CC];
    int g = blockIdx.x, t = threadIdx.x;  // 256 threads
    for (int i = t; i < LL * CC; i += 256) {
        int layer = i >> 7, c = i & 127;
        fused[i] = g_pool[layer * G * CC + g * CC + c];
    }
    if (t < CC) rootv[t] = root[g * CC + t];
    __syncthreads();

    float gr = b_ih[t], gz = b_ih[HH + t], gn = b_ih[2 * HH + t];
    const float* wr = w_ih + (size_t)t            * (LL * CC);
    const float* wz = w_ih + (size_t)(HH + t)     * (LL * CC);
    const float* wn = w_ih + (size_t)(2 * HH + t) * (LL * CC);
    for (int j = 0; j < LL * CC; j++) {
        float f = fused[j];
        gr += wr[j] * f; gz += wz[j] * f; gn += wn[j] * f;
    }
    float r  = 1.0f / (1.0f + expf(-(gr + b_hh[t])));
    float z  = 1.0f / (1.0f + expf(-(gz + b_hh[HH + t])));
    float nc = tanhf(gn + r * b_hh[2 * HH + t]);
    hgru[t] = (1.0f - z) * nc;
    __syncthreads();

    if (t < CC) {
        float acc = b_fin[t];
        const float* wf = w_fin + (size_t)t * HH;
        for (int j = 0; j < HH; j++) acc += wf[j] * hgru[j];
        float re = b_root[t];
        const float* wo = w_root + (size_t)t * CC;
        for (int j = 0; j < CC; j++) re += wo[j] * rootv[j];
        float a = *alpha_p;
        out[g * CC + t] = a * acc + (1.0f - a) * re;
    }
}

// ---------------- launch ----------------

extern "C" void kernel_launch(void* const* d_in, const int* in_sizes, int n_in,
                              void* d_out, int out_size)
{
    const float* x      = (const float*)d_in[0];
    const int*   ei     = (const int*)  d_in[1];
    const float* root   = (const float*)d_in[3];
    const float* att_l  = (const float*)d_in[4];
    const float* att_r  = (const float*)d_in[5];
    const float* w_ih   = (const float*)d_in[6];
    const float* b_ih   = (const float*)d_in[8];
    const float* b_hh   = (const float*)d_in[9];
    const float* w_fin  = (const float*)d_in[10];
    const float* b_fin  = (const float*)d_in[11];
    const float* w_root = (const float*)d_in[12];
    const float* b_root = (const float*)d_in[13];
    const float* alpha  = (const float*)d_in[14];
    float* out = (float*)d_out;

    int E = in_sizes[1] / 2;
    const int* src0 = ei;
    const int* dst0 = ei + E;

    float *acc, *cur;
    int *srcA, *dstA, *srcB, *dstB, *cnt, *oidxA, *oidxB;
    cudaGetSymbolAddress((void**)&acc,   g_acc);
    cudaGetSymbolAddress((void**)&cur,   g_cur);
    cudaGetSymbolAddress((void**)&srcA,  g_srcA);
    cudaGetSymbolAddress((void**)&dstA,  g_dstA);
    cudaGetSymbolAddress((void**)&srcB,  g_srcB);
    cudaGetSymbolAddress((void**)&dstB,  g_dstB);
    cudaGetSymbolAddress((void**)&cnt,   g_cnt);
    cudaGetSymbolAddress((void**)&oidxA, g_oidxA);
    cudaGetSymbolAddress((void**)&oidxB, g_oidxB);

    cudaFuncSetAttribute(k_sort, cudaFuncAttributeMaxDynamicSharedMemorySize, 64 * 1024);

    // ---------- Layer 0 (n = 131072, npg = 16384) ----------
    k_zero    <<<131072 / 256, 256>>>(131072, 1);
    k_degree  <<<1024, 256>>>(src0, dst0, E, nullptr);
    k_scan1   <<<128, 1024>>>();
    k_scan2   <<<1, 128>>>(128);
    k_scatter <<<1024, 256>>>(src0, dst0, E, nullptr);
    k_nodeprep<<<131072 / 8, 256>>>(x, att_l, att_r, 131072);
    k_agg     <<<131072 / 8, 256>>>(x, x, nullptr, 14, 0);
    k_sort    <<<8, 1024, 16384 * 4>>>(16384, 8192);
    k_gather  <<<65536 / 8, 256>>>(acc, cur, nullptr, oidxA, 65536);
    k_compact <<<1024, 256>>>(src0, dst0, E, nullptr, srcA, dstA, cnt + 0);

    // ---------- Layer 1 (n = 65536, npg = 8192) ----------
    k_zero    <<<65536 / 256, 256>>>(65536, 0);
    k_degree  <<<1024, 256>>>(srcA, dstA, 0, cnt + 0);
    k_scan1   <<<64, 1024>>>();
    k_scan2   <<<1, 128>>>(64);
    k_scatter <<<1024, 256>>>(srcA, dstA, 0, cnt + 0);
    k_nodeprep<<<65536 / 8, 256>>>(cur, att_l + CC, att_r + CC, 65536);
    k_agg     <<<65536 / 8, 256>>>(cur, x, oidxA, 13, 1);
    k_sort    <<<8, 1024, 8192 * 4>>>(8192, 4096);
    k_gather  <<<32768 / 8, 256>>>(acc, cur, oidxA, oidxB, 32768);
    k_compact <<<1024, 256>>>(srcA, dstA, 0, cnt + 0, srcB, dstB, cnt + 1);

    // ---------- Layer 2 (n = 32768, npg = 4096) ----------
    k_zero    <<<32768 / 256, 256>>>(32768, 0);
    k_degree  <<<1024, 256>>>(srcB, dstB, 0, cnt + 1);
    k_scan1   <<<32, 1024>>>();
    k_scan2   <<<1, 128>>>(32);
    k_scatter <<<1024, 256>>>(srcB, dstB, 0, cnt + 1);
    k_nodeprep<<<32768 / 8, 256>>>(cur, att_l + 2 * CC, att_r + 2 * CC, 32768);
    k_agg     <<<32768 / 8, 256>>>(cur, x, oidxB, 12, 2);

    // ---------- Head ----------
    k_head<<<G, 256>>>(w_ih, b_ih, b_hh, w_fin, b_fin, w_root, b_root,
                       root, alpha, out);
}

// round 3
// speedup vs baseline: 1.4337x; 1.2619x over previous
#include <cuda_runtime.h>

#define G       8
#define N0      16384
#define CC      128
#define LL      3
#define HH      256
#define EPS_FA  0.1f
#define EMAX    1048576
#define NMAX    131072
#define SBINS   512            // score histogram bins (out-degree << 512 always)

// ---------------- scratch (device globals; no allocations) ----------------
__device__ float g_acc [NMAX * CC];          // h output for current layer (64MB)
__device__ float g_cur [65536 * CC];         // cur features from layer 1 on (32MB)
__device__ int   g_srcA[EMAX], g_dstA[EMAX];
__device__ int   g_srcB[EMAX], g_dstB[EMAX];
__device__ int   g_csr [EMAX];               // CSR src lists (by dst)
__device__ float g_al[NMAX], g_ar[NMAX], g_dinv[NMAX];
__device__ int   g_deg[NMAX], g_score[NMAX], g_fill[NMAX];
__device__ int   g_offs[NMAX], g_bsum[256];
__device__ int   g_nmap[NMAX];
__device__ int   g_perm[65536];
__device__ int   g_oidxA[65536], g_oidxB[32768];
__device__ int   g_seq[NMAX];
__device__ int   g_chist[512 * SBINS];       // per-chunk score histograms (max 512 chunks)
__device__ int   g_cntgt[G * SBINS];
__device__ float g_pool[LL * G * CC];
__device__ int   g_cnt[2];

// ---------------- kernels ----------------

__global__ void k_zero(int n, int first)
{
    int i = blockIdx.x * blockDim.x + threadIdx.x;
    if (i < n) { g_deg[i] = 0; g_score[i] = 0; g_fill[i] = 0; }
    if (first) {
        if (i < LL * G * CC) g_pool[i] = 0.0f;
        if (i < 2) g_cnt[i] = 0;
    }
}

// out-degree (score) over src, in-degree (deg) over dst  (layer 0 only)
__global__ void k_degree(const int* __restrict__ src, const int* __restrict__ dst, int E)
{
    for (int e = blockIdx.x * blockDim.x + threadIdx.x; e < E;
         e += gridDim.x * blockDim.x) {
        atomicAdd(&g_deg[dst[e]], 1);
        atomicAdd(&g_score[src[e]], 1);
    }
}

// two-level exclusive scan of deg
__global__ void k_scan1()
{
    __shared__ int sh[1024];
    int tid = threadIdx.x;
    int i = blockIdx.x * 1024 + tid;
    int v = g_deg[i];
    sh[tid] = v;
    __syncthreads();
    int acc = v;
#pragma unroll
    for (int off = 1; off < 1024; off <<= 1) {
        int add = (tid >= off) ? sh[tid - off] : 0;
        __syncthreads();
        acc += add;
        sh[tid] = acc;
        __syncthreads();
    }
    g_offs[i] = acc - v;
    if (tid == 1023) g_bsum[blockIdx.x] = acc;
}

__global__ void k_scan2(int nb)
{
    __shared__ int sh[128];
    int tid = threadIdx.x;
    int v = (tid < nb) ? g_bsum[tid] : 0;
    sh[tid] = v;
    __syncthreads();
    int acc = v;
#pragma unroll
    for (int off = 1; off < 128; off <<= 1) {
        int add = (tid >= off) ? sh[tid - off] : 0;
        __syncthreads();
        acc += add;
        sh[tid] = acc;
        __syncthreads();
    }
    if (tid < nb) g_bsum[tid] = acc - v;
}

// scatter edges into CSR-by-dst
__global__ void k_scatter(const int* __restrict__ src, const int* __restrict__ dst,
                          int ecnt_fixed, const int* __restrict__ ecnt_ptr)
{
    int E = ecnt_ptr ? *ecnt_ptr : ecnt_fixed;
    for (int e = blockIdx.x * blockDim.x + threadIdx.x; e < E;
         e += gridDim.x * blockDim.x) {
        int d = dst[e];
        int p = atomicAdd(&g_fill[d], 1);
        g_csr[g_offs[d] + g_bsum[d >> 10] + p] = src[e];
    }
}

// layer-0 node prep: al, ar dots and dinv
__global__ void k_nodeprep(const float* __restrict__ cur,
                           const float* __restrict__ attl, const float* __restrict__ attr,
                           int n)
{
    int warp = (blockIdx.x * blockDim.x + threadIdx.x) >> 5;
    int lane = threadIdx.x & 31;
    if (warp >= n) return;
    float4 cv = __ldg((const float4*)(cur + (size_t)warp * CC) + lane);
    float4 lv = ((const float4*)attl)[lane];
    float4 rv = ((const float4*)attr)[lane];
    float al = cv.x*lv.x + cv.y*lv.y + cv.z*lv.z + cv.w*lv.w;
    float ar = cv.x*rv.x + cv.y*rv.y + cv.z*rv.z + cv.w*rv.w;
#pragma unroll
    for (int o = 16; o; o >>= 1) {
        al += __shfl_xor_sync(0xffffffffu, al, o);
        ar += __shfl_xor_sync(0xffffffffu, ar, o);
    }
    if (lane == 0) {
        g_al[warp]   = al;
        g_ar[warp]   = ar;
        g_dinv[warp] = rsqrtf((float)g_deg[warp] + 1.0f);
    }
}

// warp per dst node: CSR register aggregation + self loop + EPS + relu + fused max-pool
__global__ void k_agg(const float* __restrict__ cur, const float* __restrict__ x,
                      const int* __restrict__ oidx, int log2npg, int layer)
{
    __shared__ unsigned smax[128];
    int tid  = threadIdx.x;
    int lane = tid & 31;
    if (tid < 128) smax[tid] = 0;
    __syncthreads();

    int d = (blockIdx.x * blockDim.x + tid) >> 5;
    int start = g_offs[d] + g_bsum[d >> 10];
    int cnt   = g_deg[d];
    float dind = g_dinv[d];
    float ald  = g_al[d];

    float4 a = {0.f, 0.f, 0.f, 0.f};
    for (int base = 0; base < cnt; base += 32) {
        int j = base + lane;
        int s = 0; float coef = 0.f;
        if (j < cnt) {
            s = g_csr[start + j];
            coef = g_dinv[s] * dind * tanhf(ald + g_ar[s]);
        }
        int m = min(32, cnt - base);
        int t = 0;
        for (; t + 4 <= m; t += 4) {
            int   s0 = __shfl_sync(0xffffffffu, s, t + 0);
            int   s1 = __shfl_sync(0xffffffffu, s, t + 1);
            int   s2 = __shfl_sync(0xffffffffu, s, t + 2);
            int   s3 = __shfl_sync(0xffffffffu, s, t + 3);
            float c0 = __shfl_sync(0xffffffffu, coef, t + 0);
            float c1 = __shfl_sync(0xffffffffu, coef, t + 1);
            float c2 = __shfl_sync(0xffffffffu, coef, t + 2);
            float c3 = __shfl_sync(0xffffffffu, coef, t + 3);
            float4 v0 = __ldg((const float4*)(cur + (size_t)s0 * CC) + lane);
            float4 v1 = __ldg((const float4*)(cur + (size_t)s1 * CC) + lane);
            float4 v2 = __ldg((const float4*)(cur + (size_t)s2 * CC) + lane);
            float4 v3 = __ldg((const float4*)(cur + (size_t)s3 * CC) + lane);
            a.x += c0*v0.x + c1*v1.x + c2*v2.x + c3*v3.x;
            a.y += c0*v0.y + c1*v1.y + c2*v2.y + c3*v3.y;
            a.z += c0*v0.z + c1*v1.z + c2*v2.z + c3*v3.z;
            a.w += c0*v0.w + c1*v1.w + c2*v2.w + c3*v3.w;
        }
        for (; t < m; t++) {
            int   ss = __shfl_sync(0xffffffffu, s, t);
            float cc = __shfl_sync(0xffffffffu, coef, t);
            float4 v = __ldg((const float4*)(cur + (size_t)ss * CC) + lane);
            a.x += cc*v.x; a.y += cc*v.y; a.z += cc*v.z; a.w += cc*v.w;
        }
    }

    float4 cv = __ldg((const float4*)(cur + (size_t)d * CC) + lane);
    float4 ov;
    if (oidx) ov = __ldg((const float4*)(x + (size_t)oidx[d] * CC) + lane);
    else      ov = cv;                      // layer 0: orig == cur row
    float c0 = dind * dind * tanhf(ald + g_ar[d]);
    a.x = fmaxf(c0*cv.x + EPS_FA*ov.x + a.x, 0.f);
    a.y = fmaxf(c0*cv.y + EPS_FA*ov.y + a.y, 0.f);
    a.z = fmaxf(c0*cv.z + EPS_FA*ov.z + a.z, 0.f);
    a.w = fmaxf(c0*cv.w + EPS_FA*ov.w + a.w, 0.f);
    ((float4*)g_acc)[(size_t)d * 32 + lane] = a;

    atomicMax(&smax[lane*4 + 0], __float_as_uint(a.x));
    atomicMax(&smax[lane*4 + 1], __float_as_uint(a.y));
    atomicMax(&smax[lane*4 + 2], __float_as_uint(a.z));
    atomicMax(&smax[lane*4 + 3], __float_as_uint(a.w));
    __syncthreads();
    if (tid < 128) {
        int g = (int)((blockIdx.x * (blockDim.x >> 5)) >> log2npg);
        atomicMax((unsigned*)&g_pool[(layer * G + g) * CC + tid], smax[tid]);
    }
}

// ---- exact stable top-k via counting rank (replaces bitonic sort) ----
// rank(i) = #{scores > s_i} + #{j<i in graph : s_j == s_i}; same order as
// sorting keys (score<<14)|(npg-1-idx) descending.

// stage 1: per-chunk (256 nodes, 1 warp) histogram + index-stable seq numbers
__global__ void k_rank1()
{
    __shared__ int hist[8][SBINS];
    int wid = threadIdx.x >> 5, lane = threadIdx.x & 31;
    int chunk = blockIdx.x * 8 + wid;
    for (int i = lane; i < SBINS; i += 32) hist[wid][i] = 0;
    __syncwarp();
    int base = chunk * 256;
#pragma unroll
    for (int r = 0; r < 8; r++) {
        int i = base + r * 32 + lane;
        int s = min(g_score[i], SBINS - 1);
        unsigned mask = __match_any_sync(0xffffffffu, s);
        int intra = __popc(mask & ((1u << lane) - 1u));
        int cur = hist[wid][s];
        __syncwarp();
        if (intra == 0) hist[wid][s] = cur + __popc(mask);
        __syncwarp();
        g_seq[i] = cur + intra;
    }
    for (int i = lane; i < SBINS; i += 32) g_chist[chunk * SBINS + i] = hist[wid][i];
}

// stage 2: per graph: chunk-bases per score (exclusive over chunks) + cnt_gt per score
__global__ void k_rank2(int nch)
{
    __shared__ int tot[SBINS];
    int g = blockIdx.x, s = threadIdx.x;
    int run = 0;
    for (int c = 0; c < nch; c++) {
        int idx = (g * nch + c) * SBINS + s;
        int v = g_chist[idx];
        g_chist[idx] = run;
        run += v;
    }
    tot[s] = run;
    __syncthreads();
    int acc = run;
    for (int off = 1; off < SBINS; off <<= 1) {
        int add = (s + off < SBINS) ? tot[s + off] : 0;
        __syncthreads();
        acc += add;
        tot[s] = acc;
        __syncthreads();
    }
    g_cntgt[g * SBINS + s] = acc - run;   // strictly-greater count
}

// stage 3: final rank -> perm/nmap; also self-zero next layer's deg/score/fill
__global__ void k_rank3(int log2npg, int kk, int zero_n)
{
    int i = blockIdx.x * blockDim.x + threadIdx.x;
    int s = min(g_score[i], SBINS - 1);
    int g = i >> log2npg;
    int chunk = i >> 8;
    int rank = g_cntgt[g * SBINS + s] + g_chist[chunk * SBINS + s] + g_seq[i];
    int nm = -1;
    if (rank < kk) {
        int neu = g * kk + rank;
        g_perm[neu] = i;
        nm = neu;
    }
    g_nmap[i] = nm;
    if (i < zero_n) { g_score[i] = 0; g_deg[i] = 0; g_fill[i] = 0; }
}

// compact surviving edges + accumulate next-layer deg/score in the same pass
__global__ void k_compactdeg(const int* __restrict__ src, const int* __restrict__ dst,
                             int ecnt_fixed, const int* __restrict__ ecnt_ptr,
                             int* __restrict__ osrc, int* __restrict__ odst,
                             int* __restrict__ cnt)
{
    int E = ecnt_ptr ? *ecnt_ptr : ecnt_fixed;
    int lane   = threadIdx.x & 31;
    int warp   = (blockIdx.x * blockDim.x + threadIdx.x) >> 5;
    int nwarps = (gridDim.x * blockDim.x) >> 5;
    for (int base = warp * 32; base < E; base += nwarps * 32) {
        int e = base + lane;
        bool keep = false; int ns = 0, nd = 0;
        if (e < E) {
            ns = g_nmap[src[e]];
            nd = g_nmap[dst[e]];
            keep = (ns >= 0) && (nd >= 0);
        }
        unsigned bal = __ballot_sync(0xffffffffu, keep);
        int tot = __popc(bal);
        int pos = 0;
        if (lane == 0 && tot) pos = atomicAdd(cnt, tot);
        pos = __shfl_sync(0xffffffffu, pos, 0);
        if (keep) {
            int off = __popc(bal & ((1u << lane) - 1u));
            osrc[pos + off] = ns;
            odst[pos + off] = nd;
            atomicAdd(&g_deg[nd], 1);
            atomicAdd(&g_score[ns], 1);
        }
    }
}

// gather kept features + compute next layer's al/ar/dinv + orig-index composition
__global__ void k_gatherprep(const float* __restrict__ h, float* __restrict__ cur_out,
                             const int* __restrict__ oidx_old, int* __restrict__ oidx_new,
                             const float* __restrict__ attl, const float* __restrict__ attr,
                             int cnt)
{
    int warp = (blockIdx.x * blockDim.x + threadIdx.x) >> 5;
    int lane = threadIdx.x & 31;
    if (warp >= cnt) return;
    int old = g_perm[warp];
    float4 v = __ldg((const float4*)(h + (size_t)old * CC) + lane);
    ((float4*)(cur_out + (size_t)warp * CC))[lane] = v;
    float4 lv = ((const float4*)attl)[lane];
    float4 rv = ((const float4*)attr)[lane];
    float al = v.x*lv.x + v.y*lv.y + v.z*lv.z + v.w*lv.w;
    float ar = v.x*rv.x + v.y*rv.y + v.z*rv.z + v.w*rv.w;
#pragma unroll
    for (int o = 16; o; o >>= 1) {
        al += __shfl_xor_sync(0xffffffffu, al, o);
        ar += __shfl_xor_sync(0xffffffffu, ar, o);
    }
    if (lane == 0) {
        g_al[warp]   = al;
        g_ar[warp]   = ar;
        g_dinv[warp] = rsqrtf((float)g_deg[warp] + 1.0f);  // next-layer deg
        oidx_new[warp] = oidx_old ? oidx_old[old] : old;
    }
}

// GRU (h0=0) + final linears + root residual
__global__ void k_head(const float* __restrict__ w_ih, const float* __restrict__ b_ih,
                       const float* __restrict__ b_hh,
                       const float* __restrict__ w_fin, const float* __restrict__ b_fin,
                       const float* __restrict__ w_root, const float* __restrict__ b_root,
                       const float* __restrict__ root, const float* __restrict__ alpha_p,
                       float* __restrict__ out)
{
    __shared__ float fused[LL * CC];
    __shared__ float hgru[HH];
    __shared__ float rootv[CC];
    int g = blockIdx.x, t = threadIdx.x;
    for (int i = t; i < LL * CC; i += 256) {
        int layer = i >> 7, c = i & 127;
        fused[i] = g_pool[layer * G * CC + g * CC + c];
    }
    if (t < CC) rootv[t] = root[g * CC + t];
    __syncthreads();

    float gr = b_ih[t], gz = b_ih[HH + t], gn = b_ih[2 * HH + t];
    const float* wr = w_ih + (size_t)t            * (LL * CC);
    const float* wz = w_ih + (size_t)(HH + t)     * (LL * CC);
    const float* wn = w_ih + (size_t)(2 * HH + t) * (LL * CC);
    for (int j = 0; j < LL * CC; j++) {
        float f = fused[j];
        gr += wr[j] * f; gz += wz[j] * f; gn += wn[j] * f;
    }
    float r  = 1.0f / (1.0f + expf(-(gr + b_hh[t])));
    float z  = 1.0f / (1.0f + expf(-(gz + b_hh[HH + t])));
    float nc = tanhf(gn + r * b_hh[2 * HH + t]);
    hgru[t] = (1.0f - z) * nc;
    __syncthreads();

    if (t < CC) {
        float acc = b_fin[t];
        const float* wf = w_fin + (size_t)t * HH;
        for (int j = 0; j < HH; j++) acc += wf[j] * hgru[j];
        float re = b_root[t];
        const float* wo = w_root + (size_t)t * CC;
        for (int j = 0; j < CC; j++) re += wo[j] * rootv[j];
        float a = *alpha_p;
        out[g * CC + t] = a * acc + (1.0f - a) * re;
    }
}

// ---------------- launch ----------------

extern "C" void kernel_launch(void* const* d_in, const int* in_sizes, int n_in,
                              void* d_out, int out_size)
{
    const float* x      = (const float*)d_in[0];
    const int*   ei     = (const int*)  d_in[1];
    const float* root   = (const float*)d_in[3];
    const float* att_l  = (const float*)d_in[4];
    const float* att_r  = (const float*)d_in[5];
    const float* w_ih   = (const float*)d_in[6];
    const float* b_ih   = (const float*)d_in[8];
    const float* b_hh   = (const float*)d_in[9];
    const float* w_fin  = (const float*)d_in[10];
    const float* b_fin  = (const float*)d_in[11];
    const float* w_root = (const float*)d_in[12];
    const float* b_root = (const float*)d_in[13];
    const float* alpha  = (const float*)d_in[14];
    float* out = (float*)d_out;

    int E = in_sizes[1] / 2;
    const int* src0 = ei;
    const int* dst0 = ei + E;

    float *acc, *cur;
    int *srcA, *dstA, *srcB, *dstB, *cnt, *oidxA, *oidxB;
    cudaGetSymbolAddress((void**)&acc,   g_acc);
    cudaGetSymbolAddress((void**)&cur,   g_cur);
    cudaGetSymbolAddress((void**)&srcA,  g_srcA);
    cudaGetSymbolAddress((void**)&dstA,  g_dstA);
    cudaGetSymbolAddress((void**)&srcB,  g_srcB);
    cudaGetSymbolAddress((void**)&dstB,  g_dstB);
    cudaGetSymbolAddress((void**)&cnt,   g_cnt);
    cudaGetSymbolAddress((void**)&oidxA, g_oidxA);
    cudaGetSymbolAddress((void**)&oidxB, g_oidxB);

    // ---------- Layer 0 (n = 131072, npg = 16384) ----------
    k_zero      <<<512, 256>>>(131072, 1);
    k_degree    <<<1024, 256>>>(src0, dst0, E);
    k_scan1     <<<128, 1024>>>();
    k_scan2     <<<1, 128>>>(128);
    k_scatter   <<<1024, 256>>>(src0, dst0, E, nullptr);
    k_nodeprep  <<<131072 / 8, 256>>>(x, att_l, att_r, 131072);
    k_agg       <<<131072 / 8, 256>>>(x, x, nullptr, 14, 0);
    k_rank1     <<<64, 256>>>();
    k_rank2     <<<G, SBINS>>>(64);
    k_rank3     <<<512, 256>>>(14, 8192, 65536);
    k_compactdeg<<<1024, 256>>>(src0, dst0, E, nullptr, srcA, dstA, cnt + 0);
    k_gatherprep<<<65536 / 8, 256>>>(acc, cur, nullptr, oidxA,
                                     att_l + CC, att_r + CC, 65536);

    // ---------- Layer 1 (n = 65536, npg = 8192) ----------
    k_scan1     <<<64, 1024>>>();
    k_scan2     <<<1, 128>>>(64);
    k_scatter   <<<1024, 256>>>(srcA, dstA, 0, cnt + 0);
    k_agg       <<<65536 / 8, 256>>>(cur, x, oidxA, 13, 1);
    k_rank1     <<<32, 256>>>();
    k_rank2     <<<G, SBINS>>>(32);
    k_rank3     <<<256, 256>>>(13, 4096, 32768);
    k_compactdeg<<<1024, 256>>>(srcA, dstA, 0, cnt + 0, srcB, dstB, cnt + 1);
    k_gatherprep<<<32768 / 8, 256>>>(acc, cur, oidxA, oidxB,
                                     att_l + 2 * CC, att_r + 2 * CC, 32768);

    // ---------- Layer 2 (n = 32768, npg = 4096) ----------
    k_scan1     <<<32, 1024>>>();
    k_scan2     <<<1, 128>>>(32);
    k_scatter   <<<1024, 256>>>(srcB, dstB, 0, cnt + 1);
    k_agg       <<<32768 / 8, 256>>>(cur, x, oidxB, 12, 2);

    // ---------- Head ----------
    k_head<<<G, 256>>>(w_ih, b_ih, b_hh, w_fin, b_fin, w_root, b_root,
                       root, alpha, out);
}

// round 4
// speedup vs baseline: 1.5036x; 1.0488x over previous
#include <cuda_runtime.h>
#include <cuda_fp16.h>

#define G       8
#define N0      16384
#define CC      128
#define LL      3
#define HH      256
#define EPS_FA  0.1f
#define EMAX    1048576
#define NMAX    131072
#define SBINS   512

// ---------------- scratch (device globals; no allocations) ----------------
__device__ float  g_acc [NMAX * CC];           // fp32 h output of current layer (64MB)
__device__ __half g_xh  [NMAX * CC];           // half copy of original x (32MB)
__device__ __half g_curh[65536 * CC];          // half cur features, layers 1/2 (16MB)
__device__ int    g_srcA[EMAX], g_dstA[EMAX];
__device__ int    g_srcB[EMAX], g_dstB[EMAX];
__device__ int    g_csr [EMAX];
__device__ float  g_al[NMAX], g_ar[NMAX];
__device__ int    g_deg[NMAX], g_score[NMAX], g_fill[NMAX];
__device__ int    g_offs[NMAX];
__device__ unsigned g_scanstate[128];
__device__ int    g_nmap[NMAX];
__device__ int    g_perm[65536];
__device__ int    g_oidxA[65536], g_oidxB[32768];
__device__ int    g_seq[NMAX];
__device__ int    g_chist[512 * SBINS];
__device__ int    g_cntgt[G * SBINS];
__device__ float  g_pool[LL * G * CC];
__device__ int    g_cnt[2];

__device__ __forceinline__ float2 h2f(unsigned u)
{
    __half2 h = *reinterpret_cast<__half2*>(&u);
    return __half22float2(h);
}

// ---------------- kernels ----------------

__global__ void k_zero(int n, int first)
{
    int i = blockIdx.x * blockDim.x + threadIdx.x;
    if (i < n) { g_deg[i] = 0; g_score[i] = 0; g_fill[i] = 0; }
    if (first) {
        if (i < LL * G * CC) g_pool[i] = 0.0f;
        if (i < 128) g_scanstate[i] = 0u;
        if (i < 2) g_cnt[i] = 0;
    }
}

// layer-0 degree
__global__ void k_degree(const int* __restrict__ src, const int* __restrict__ dst, int E)
{
    for (int e = blockIdx.x * blockDim.x + threadIdx.x; e < E;
         e += gridDim.x * blockDim.x) {
        atomicAdd(&g_deg[dst[e]], 1);
        atomicAdd(&g_score[src[e]], 1);
    }
}

// single-pass exclusive scan of deg (decoupled lookback); grid nb x 1024
__global__ void k_scan()
{
    __shared__ int sh[1024];
    __shared__ int s_base;
    int tid = threadIdx.x, b = blockIdx.x;
    int i = b * 1024 + tid;
    int v = g_deg[i];
    sh[tid] = v;
    __syncthreads();
    int acc = v;
#pragma unroll
    for (int off = 1; off < 1024; off <<= 1) {
        int add = (tid >= off) ? sh[tid - off] : 0;
        __syncthreads();
        acc += add;
        sh[tid] = acc;
        __syncthreads();
    }
    int total = sh[1023];
    if (tid == 0) {
        if (b == 0) {
            atomicExch(&g_scanstate[0], 0x80000000u | (unsigned)total);
            s_base = 0;
        } else {
            atomicExch(&g_scanstate[b], 0x40000000u | (unsigned)total);
            int base = 0;
            for (int j = b - 1; j >= 0; j--) {
                unsigned s;
                do { s = atomicAdd(&g_scanstate[j], 0u); } while (s == 0u);
                base += (int)(s & 0x3FFFFFFFu);
                if (s & 0x80000000u) break;
            }
            atomicExch(&g_scanstate[b], 0x80000000u | (unsigned)(base + total));
            s_base = base;
        }
    }
    __syncthreads();
    g_offs[i] = s_base + acc - v;
}

// scatter edges into CSR-by-dst
__global__ void k_scatter(const int* __restrict__ src, const int* __restrict__ dst,
                          int ecnt_fixed, const int* __restrict__ ecnt_ptr)
{
    int E = ecnt_ptr ? *ecnt_ptr : ecnt_fixed;
    for (int e = blockIdx.x * blockDim.x + threadIdx.x; e < E;
         e += gridDim.x * blockDim.x) {
        int d = dst[e];
        int p = atomicAdd(&g_fill[d], 1);
        g_csr[g_offs[d] + p] = src[e];
    }
}

// layer-0 node prep: al/ar dots + half copy of x (no deg dependence)
__global__ void k_nodeprep(const float* __restrict__ x,
                           const float* __restrict__ attl, const float* __restrict__ attr,
                           int n)
{
    int warp = (blockIdx.x * blockDim.x + threadIdx.x) >> 5;
    int lane = threadIdx.x & 31;
    if (warp >= n) return;
    float4 cv = __ldg((const float4*)(x + (size_t)warp * CC) + lane);
    float4 lv = ((const float4*)attl)[lane];
    float4 rv = ((const float4*)attr)[lane];
    float al = cv.x*lv.x + cv.y*lv.y + cv.z*lv.z + cv.w*lv.w;
    float ar = cv.x*rv.x + cv.y*rv.y + cv.z*rv.z + cv.w*rv.w;
#pragma unroll
    for (int o = 16; o; o >>= 1) {
        al += __shfl_xor_sync(0xffffffffu, al, o);
        ar += __shfl_xor_sync(0xffffffffu, ar, o);
    }
    if (lane == 0) { g_al[warp] = al; g_ar[warp] = ar; }
    uint2 h;
    *reinterpret_cast<__half2*>(&h.x) = __floats2half2_rn(cv.x, cv.y);
    *reinterpret_cast<__half2*>(&h.y) = __floats2half2_rn(cv.z, cv.w);
    ((uint2*)(g_xh + (size_t)warp * CC))[lane] = h;
}

// warp per dst: CSR aggregation on half features + self loop + EPS + relu + fused pool
__global__ void k_agg(const __half* __restrict__ curh, const int* __restrict__ oidx,
                      int log2npg, int layer)
{
    __shared__ unsigned smax[128];
    int tid  = threadIdx.x;
    int lane = tid & 31;
    if (tid < 128) smax[tid] = 0;
    __syncthreads();

    int d = (blockIdx.x * blockDim.x + tid) >> 5;
    int start = g_offs[d];
    int cnt   = g_deg[d];
    float dind = rsqrtf((float)cnt + 1.0f);
    float ald  = g_al[d];

    float4 a = {0.f, 0.f, 0.f, 0.f};
    for (int base = 0; base < cnt; base += 32) {
        int j = base + lane;
        int s = 0; float coef = 0.f;
        if (j < cnt) {
            s = g_csr[start + j];
            coef = rsqrtf((float)g_deg[s] + 1.0f) * dind * tanhf(ald + g_ar[s]);
        }
        int m = min(32, cnt - base);
        int t = 0;
        for (; t + 4 <= m; t += 4) {
            int   s0 = __shfl_sync(0xffffffffu, s, t + 0);
            int   s1 = __shfl_sync(0xffffffffu, s, t + 1);
            int   s2 = __shfl_sync(0xffffffffu, s, t + 2);
            int   s3 = __shfl_sync(0xffffffffu, s, t + 3);
            float c0 = __shfl_sync(0xffffffffu, coef, t + 0);
            float c1 = __shfl_sync(0xffffffffu, coef, t + 1);
            float c2 = __shfl_sync(0xffffffffu, coef, t + 2);
            float c3 = __shfl_sync(0xffffffffu, coef, t + 3);
            uint2 p0 = __ldg((const uint2*)(curh + (size_t)s0 * CC) + lane);
            uint2 p1 = __ldg((const uint2*)(curh + (size_t)s1 * CC) + lane);
            uint2 p2 = __ldg((const uint2*)(curh + (size_t)s2 * CC) + lane);
            uint2 p3 = __ldg((const uint2*)(curh + (size_t)s3 * CC) + lane);
            float2 f;
            f = h2f(p0.x); a.x += c0*f.x; a.y += c0*f.y;
            f = h2f(p0.y); a.z += c0*f.x; a.w += c0*f.y;
            f = h2f(p1.x); a.x += c1*f.x; a.y += c1*f.y;
            f = h2f(p1.y); a.z += c1*f.x; a.w += c1*f.y;
            f = h2f(p2.x); a.x += c2*f.x; a.y += c2*f.y;
            f = h2f(p2.y); a.z += c2*f.x; a.w += c2*f.y;
            f = h2f(p3.x); a.x += c3*f.x; a.y += c3*f.y;
            f = h2f(p3.y); a.z += c3*f.x; a.w += c3*f.y;
        }
        for (; t < m; t++) {
            int   ss = __shfl_sync(0xffffffffu, s, t);
            float cc = __shfl_sync(0xffffffffu, coef, t);
            uint2 p = __ldg((const uint2*)(curh + (size_t)ss * CC) + lane);
            float2 f;
            f = h2f(p.x); a.x += cc*f.x; a.y += cc*f.y;
            f = h2f(p.y); a.z += cc*f.x; a.w += cc*f.y;
        }
    }

    uint2 pc = __ldg((const uint2*)(curh + (size_t)d * CC) + lane);
    uint2 po = oidx ? __ldg((const uint2*)(g_xh + (size_t)__ldg(&oidx[d]) * CC) + lane)
                    : pc;
    float2 c01 = h2f(pc.x), c23 = h2f(pc.y);
    float2 o01 = h2f(po.x), o23 = h2f(po.y);
    float c0 = dind * dind * tanhf(ald + g_ar[d]);
    a.x = fmaxf(c0*c01.x + EPS_FA*o01.x + a.x, 0.f);
    a.y = fmaxf(c0*c01.y + EPS_FA*o01.y + a.y, 0.f);
    a.z = fmaxf(c0*c23.x + EPS_FA*o23.x + a.z, 0.f);
    a.w = fmaxf(c0*c23.y + EPS_FA*o23.y + a.w, 0.f);
    ((float4*)g_acc)[(size_t)d * 32 + lane] = a;

    atomicMax(&smax[lane*4 + 0], __float_as_uint(a.x));
    atomicMax(&smax[lane*4 + 1], __float_as_uint(a.y));
    atomicMax(&smax[lane*4 + 2], __float_as_uint(a.z));
    atomicMax(&smax[lane*4 + 3], __float_as_uint(a.w));
    __syncthreads();
    if (tid < 128) {
        int g = (int)((blockIdx.x * (blockDim.x >> 5)) >> log2npg);
        atomicMax((unsigned*)&g_pool[(layer * G + g) * CC + tid], smax[tid]);
    }
}

// ---- exact stable top-k via counting rank ----
__global__ void k_rank1()
{
    __shared__ int hist[8][SBINS];
    int wid = threadIdx.x >> 5, lane = threadIdx.x & 31;
    int chunk = blockIdx.x * 8 + wid;
    for (int i = lane; i < SBINS; i += 32) hist[wid][i] = 0;
    __syncwarp();
    int base = chunk * 256;
#pragma unroll
    for (int r = 0; r < 8; r++) {
        int i = base + r * 32 + lane;
        int s = min(g_score[i], SBINS - 1);
        unsigned mask = __match_any_sync(0xffffffffu, s);
        int intra = __popc(mask & ((1u << lane) - 1u));
        int cur = hist[wid][s];
        __syncwarp();
        if (intra == 0) hist[wid][s] = cur + __popc(mask);
        __syncwarp();
        g_seq[i] = cur + intra;
    }
    for (int i = lane; i < SBINS; i += 32) g_chist[chunk * SBINS + i] = hist[wid][i];
}

__global__ void k_rank2(int nch)
{
    __shared__ int tot[SBINS];
    int g = blockIdx.x, s = threadIdx.x;
    int run = 0;
    for (int c = 0; c < nch; c++) {
        int idx = (g * nch + c) * SBINS + s;
        int v = g_chist[idx];
        g_chist[idx] = run;
        run += v;
    }
    tot[s] = run;
    __syncthreads();
    int acc = run;
    for (int off = 1; off < SBINS; off <<= 1) {
        int add = (s + off < SBINS) ? tot[s + off] : 0;
        __syncthreads();
        acc += add;
        tot[s] = acc;
        __syncthreads();
    }
    g_cntgt[g * SBINS + s] = acc - run;
}

__global__ void k_rank3(int log2npg, int kk, int zero_n)
{
    int i = blockIdx.x * blockDim.x + threadIdx.x;
    int s = min(g_score[i], SBINS - 1);
    int g = i >> log2npg;
    int chunk = i >> 8;
    int rank = g_cntgt[g * SBINS + s] + g_chist[chunk * SBINS + s] + g_seq[i];
    int nm = -1;
    if (rank < kk) {
        int neu = g * kk + rank;
        g_perm[neu] = i;
        nm = neu;
    }
    g_nmap[i] = nm;
    if (i < zero_n) { g_score[i] = 0; g_deg[i] = 0; g_fill[i] = 0; }
    if (blockIdx.x == 0 && threadIdx.x < 128) g_scanstate[threadIdx.x] = 0u;
}

// compact surviving edges + next-layer deg/score
__global__ void k_compactdeg(const int* __restrict__ src, const int* __restrict__ dst,
                             int ecnt_fixed, const int* __restrict__ ecnt_ptr,
                             int* __restrict__ osrc, int* __restrict__ odst,
                             int* __restrict__ cnt)
{
    int E = ecnt_ptr ? *ecnt_ptr : ecnt_fixed;
    int lane   = threadIdx.x & 31;
    int warp   = (blockIdx.x * blockDim.x + threadIdx.x) >> 5;
    int nwarps = (gridDim.x * blockDim.x) >> 5;
    for (int base = warp * 32; base < E; base += nwarps * 32) {
        int e = base + lane;
        bool keep = false; int ns = 0, nd = 0;
        if (e < E) {
            ns = g_nmap[src[e]];
            nd = g_nmap[dst[e]];
            keep = (ns >= 0) && (nd >= 0);
        }
        unsigned bal = __ballot_sync(0xffffffffu, keep);
        int tot = __popc(bal);
        int pos = 0;
        if (lane == 0 && tot) pos = atomicAdd(cnt, tot);
        pos = __shfl_sync(0xffffffffu, pos, 0);
        if (keep) {
            int off = __popc(bal & ((1u << lane) - 1u));
            osrc[pos + off] = ns;
            odst[pos + off] = nd;
            atomicAdd(&g_deg[nd], 1);
            atomicAdd(&g_score[ns], 1);
        }
    }
}

// gather kept features (fp32 h -> half cur) + next al/ar + orig-index composition
__global__ void k_gatherprep(const float* __restrict__ h, __half* __restrict__ cur_out,
                             const int* __restrict__ oidx_old, int* __restrict__ oidx_new,
                             const float* __restrict__ attl, const float* __restrict__ attr,
                             int cnt)
{
    int warp = (blockIdx.x * blockDim.x + threadIdx.x) >> 5;
    int lane = threadIdx.x & 31;
    if (warp >= cnt) return;
    int old = g_perm[warp];
    float4 v = __ldg((const float4*)(h + (size_t)old * CC) + lane);
    uint2 hh;
    *reinterpret_cast<__half2*>(&hh.x) = __floats2half2_rn(v.x, v.y);
    *reinterpret_cast<__half2*>(&hh.y) = __floats2half2_rn(v.z, v.w);
    ((uint2*)(cur_out + (size_t)warp * CC))[lane] = hh;
    float4 lv = ((const float4*)attl)[lane];
    float4 rv = ((const float4*)attr)[lane];
    float al = v.x*lv.x + v.y*lv.y + v.z*lv.z + v.w*lv.w;
    float ar = v.x*rv.x + v.y*rv.y + v.z*rv.z + v.w*rv.w;
#pragma unroll
    for (int o = 16; o; o >>= 1) {
        al += __shfl_xor_sync(0xffffffffu, al, o);
        ar += __shfl_xor_sync(0xffffffffu, ar, o);
    }
    if (lane == 0) {
        g_al[warp] = al;
        g_ar[warp] = ar;
        oidx_new[warp] = oidx_old ? oidx_old[old] : old;
    }
}

// GRU (h0=0) + final linears + root residual
__global__ void k_head(const float* __restrict__ w_ih, const float* __restrict__ b_ih,
                       const float* __restrict__ b_hh,
                       const float* __restrict__ w_fin, const float* __restrict__ b_fin,
                       const float* __restrict__ w_root, const float* __restrict__ b_root,
                       const float* __restrict__ root, const float* __restrict__ alpha_p,
                       float* __restrict__ out)
{
    __shared__ float fused[LL * CC];
    __shared__ float hgru[HH];
    __shared__ float rootv[CC];
    int g = blockIdx.x, t = threadIdx.x;
    for (int i = t; i < LL * CC; i += 256) {
        int layer = i >> 7, c = i & 127;
        fused[i] = g_pool[layer * G * CC + g * CC + c];
    }
    if (t < CC) rootv[t] = root[g * CC + t];
    __syncthreads();

    float gr = b_ih[t], gz = b_ih[HH + t], gn = b_ih[2 * HH + t];
    const float* wr = w_ih + (size_t)t            * (LL * CC);
    const float* wz = w_ih + (size_t)(HH + t)     * (LL * CC);
    const float* wn = w_ih + (size_t)(2 * HH + t) * (LL * CC);
    for (int j = 0; j < LL * CC; j++) {
        float f = fused[j];
        gr += wr[j] * f; gz += wz[j] * f; gn += wn[j] * f;
    }
    float r  = 1.0f / (1.0f + expf(-(gr + b_hh[t])));
    float z  = 1.0f / (1.0f + expf(-(gz + b_hh[HH + t])));
    float nc = tanhf(gn + r * b_hh[2 * HH + t]);
    hgru[t] = (1.0f - z) * nc;
    __syncthreads();

    if (t < CC) {
        float acc = b_fin[t];
        const float* wf = w_fin + (size_t)t * HH;
        for (int j = 0; j < HH; j++) acc += wf[j] * hgru[j];
        float re = b_root[t];
        const float* wo = w_root + (size_t)t * CC;
        for (int j = 0; j < CC; j++) re += wo[j] * rootv[j];
        float a = *alpha_p;
        out[g * CC + t] = a * acc + (1.0f - a) * re;
    }
}

// ---------------- launch ----------------

extern "C" void kernel_launch(void* const* d_in, const int* in_sizes, int n_in,
                              void* d_out, int out_size)
{
    const float* x      = (const float*)d_in[0];
    const int*   ei     = (const int*)  d_in[1];
    const float* root   = (const float*)d_in[3];
    const float* att_l  = (const float*)d_in[4];
    const float* att_r  = (const float*)d_in[5];
    const float* w_ih   = (const float*)d_in[6];
    const float* b_ih   = (const float*)d_in[8];
    const float* b_hh   = (const float*)d_in[9];
    const float* w_fin  = (const float*)d_in[10];
    const float* b_fin  = (const float*)d_in[11];
    const float* w_root = (const float*)d_in[12];
    const float* b_root = (const float*)d_in[13];
    const float* alpha  = (const float*)d_in[14];
    float* out = (float*)d_out;

    int E = in_sizes[1] / 2;
    const int* src0 = ei;
    const int* dst0 = ei + E;

    float *acc;
    __half *xh, *curh;
    int *srcA, *dstA, *srcB, *dstB, *cnt, *oidxA, *oidxB;
    cudaGetSymbolAddress((void**)&acc,   g_acc);
    cudaGetSymbolAddress((void**)&xh,    g_xh);
    cudaGetSymbolAddress((void**)&curh,  g_curh);
    cudaGetSymbolAddress((void**)&srcA,  g_srcA);
    cudaGetSymbolAddress((void**)&dstA,  g_dstA);
    cudaGetSymbolAddress((void**)&srcB,  g_srcB);
    cudaGetSymbolAddress((void**)&dstB,  g_dstB);
    cudaGetSymbolAddress((void**)&cnt,   g_cnt);
    cudaGetSymbolAddress((void**)&oidxA, g_oidxA);
    cudaGetSymbolAddress((void**)&oidxB, g_oidxB);

    // one-time side resources (streams/events are not device memory)
    static cudaStream_t sa = nullptr;
    static cudaEvent_t ef[3], ej[3];
    if (!sa) {
        cudaStreamCreateWithFlags(&sa, cudaStreamNonBlocking);
        for (int i = 0; i < 3; i++) {
            cudaEventCreateWithFlags(&ef[i], cudaEventDisableTiming);
            cudaEventCreateWithFlags(&ej[i], cudaEventDisableTiming);
        }
    }

    // ---------- Layer 0 (n = 131072, npg = 16384) ----------
    k_zero<<<512, 256>>>(131072, 1);
    cudaEventRecord(ef[0], 0);
    cudaStreamWaitEvent(sa, ef[0], 0);
    k_nodeprep<<<131072 / 8, 256, 0, sa>>>(x, att_l, att_r, 131072);
    cudaEventRecord(ej[0], sa);
    k_degree  <<<1024, 256>>>(src0, dst0, E);
    k_scan    <<<128, 1024>>>();
    k_scatter <<<1024, 256>>>(src0, dst0, E, nullptr);
    cudaStreamWaitEvent(0, ej[0], 0);
    k_agg     <<<131072 / 8, 256>>>(xh, nullptr, 14, 0);
    k_rank1   <<<64, 256>>>();
    k_rank2   <<<G, SBINS>>>(64);
    k_rank3   <<<512, 256>>>(14, 8192, 65536);

    // ---------- Layer 1 (n = 65536, npg = 8192) ----------
    cudaEventRecord(ef[1], 0);
    cudaStreamWaitEvent(sa, ef[1], 0);
    k_gatherprep<<<65536 / 8, 256, 0, sa>>>(acc, curh, nullptr, oidxA,
                                            att_l + CC, att_r + CC, 65536);
    cudaEventRecord(ej[1], sa);
    k_compactdeg<<<1024, 256>>>(src0, dst0, E, nullptr, srcA, dstA, cnt + 0);
    k_scan      <<<64, 1024>>>();
    k_scatter   <<<1024, 256>>>(srcA, dstA, 0, cnt + 0);
    cudaStreamWaitEvent(0, ej[1], 0);
    k_agg       <<<65536 / 8, 256>>>(curh, oidxA, 13, 1);
    k_rank1     <<<32, 256>>>();
    k_rank2     <<<G, SBINS>>>(32);
    k_rank3     <<<256, 256>>>(13, 4096, 32768);

    // ---------- Layer 2 (n = 32768, npg = 4096) ----------
    cudaEventRecord(ef[2], 0);
    cudaStreamWaitEvent(sa, ef[2], 0);
    k_gatherprep<<<32768 / 8, 256, 0, sa>>>(acc, curh, oidxA, oidxB,
                                            att_l + 2 * CC, att_r + 2 * CC, 32768);
    cudaEventRecord(ej[2], sa);
    k_compactdeg<<<1024, 256>>>(srcA, dstA, 0, cnt + 0, srcB, dstB, cnt + 1);
    k_scan      <<<32, 1024>>>();
    k_scatter   <<<1024, 256>>>(srcB, dstB, 0, cnt + 1);
    cudaStreamWaitEvent(0, ej[2], 0);
    k_agg       <<<32768 / 8, 256>>>(curh, oidxB, 12, 2);

    // ---------- Head ----------
    k_head<<<G, 256>>>(w_ih, b_ih, b_hh, w_fin, b_fin, w_root, b_root,
                       root, alpha, out);
}

// round 5
// speedup vs baseline: 1.5656x; 1.0412x over previous
#include <cuda_runtime.h>
#include <cuda_fp16.h>

#define G       8
#define N0      16384
#define CC      128
#define LL      3
#define HH      256
#define EPS_FA  0.1f
#define EMAX    1048576
#define NMAX    131072
#define SBINS   512

// ---------------- scratch (device globals; no allocations) ----------------
__device__ float  g_acc [NMAX * CC];           // fp32 h output of current layer
__device__ __half g_xh  [NMAX * CC];           // half copy of original x
__device__ __half g_curh[65536 * CC];          // half cur features, layers 1/2
__device__ int    g_srcA[EMAX], g_dstA[EMAX];
__device__ int    g_srcB[EMAX], g_dstB[EMAX];
__device__ int    g_csr0[EMAX], g_csr1[EMAX], g_csr2[EMAX];
__device__ float  g_al[NMAX], g_ar[NMAX];
__device__ __align__(16) int g_deg0[131072], g_deg1[65536], g_deg2[32768];
__device__ int    g_scoreA[131072], g_scoreB[65536];
__device__ int    g_fill0[131072], g_fill1[65536], g_fill2[32768];
__device__ __align__(16) int g_offs0[131072], g_offs1[65536], g_offs2[32768];
__device__ unsigned g_state0[64], g_state1[64], g_state2[64];
__device__ int    g_nmap[131072];
__device__ int    g_permA[65536], g_permB[32768];
__device__ int    g_oidxA[65536], g_oidxB[32768];
__device__ int    g_seq[131072];
__device__ int    g_chist[512 * SBINS];
__device__ int    g_cntgt[G * SBINS];
__device__ float  g_pool[LL * G * CC];
__device__ int    g_cnt[2];

__device__ __forceinline__ float2 h2f(unsigned u)
{
    __half2 h = *reinterpret_cast<__half2*>(&u);
    return __half22float2(h);
}

// ---------------- kernels ----------------

__global__ void k_zero()
{
    int i = blockIdx.x * blockDim.x + threadIdx.x;   // 131072 threads
    g_deg0[i] = 0; g_fill0[i] = 0; g_scoreA[i] = 0;
    if (i < 65536) { g_deg1[i] = 0; g_fill1[i] = 0; g_scoreB[i] = 0; }
    if (i < 32768) { g_deg2[i] = 0; g_fill2[i] = 0; }
    if (i < LL * G * CC) g_pool[i] = 0.0f;
    if (i < 64) { g_state0[i] = 0u; g_state1[i] = 0u; g_state2[i] = 0u; }
    if (i < 2) g_cnt[i] = 0;
}

// layer-0 degree: in-deg over dst, out-deg (score) over src
__global__ void k_degree(const int* __restrict__ src, const int* __restrict__ dst, int E)
{
    for (int e = blockIdx.x * blockDim.x + threadIdx.x; e < E;
         e += gridDim.x * blockDim.x) {
        atomicAdd(&g_deg0[dst[e]], 1);
        atomicAdd(&g_scoreA[src[e]], 1);
    }
}

// single-pass exclusive scan, 4 items/thread, warp-parallel decoupled lookback
__global__ void k_scan(const int* __restrict__ deg, int* __restrict__ offs,
                       unsigned* __restrict__ state)
{
    __shared__ int sh[1024];
    __shared__ int s_base;
    int tid = threadIdx.x, b = blockIdx.x;
    int gi = b * 4096 + tid * 4;
    int4 v = *(const int4*)(deg + gi);
    int tsum = v.x + v.y + v.z + v.w;
    sh[tid] = tsum;
    __syncthreads();
    int acc = tsum;
#pragma unroll
    for (int off = 1; off < 1024; off <<= 1) {
        int add = (tid >= off) ? sh[tid - off] : 0;
        __syncthreads();
        acc += add;
        sh[tid] = acc;
        __syncthreads();
    }
    int total = sh[1023];
    if (tid == 0 && b > 0)
        atomicExch(&state[b], 0x40000000u | (unsigned)total);   // aggregate ready
    if (tid < 32) {
        int base = 0;
        if (b > 0) {
            int idx = b - 1 - tid;
            while (true) {
                unsigned s = 0;
                if (idx >= 0) { do { s = atomicAdd(&state[idx], 0u); } while (s == 0u); }
                unsigned pm = __ballot_sync(0xffffffffu, idx >= 0 && (s & 0x80000000u));
                int firstP = pm ? (__ffs(pm) - 1) : 32;
                int c = (idx >= 0 && tid <= firstP) ? (int)(s & 0x3FFFFFFFu) : 0;
#pragma unroll
                for (int o = 16; o; o >>= 1) c += __shfl_xor_sync(0xffffffffu, c, o);
                base += c;
                if (pm) break;
                idx -= 32;
            }
        }
        if (tid == 0) {
            atomicExch(&state[b], 0x80000000u | (unsigned)(base + total)); // prefix ready
            s_base = base;
        }
    }
    __syncthreads();
    int excl = s_base + acc - tsum;
    int4 o;
    o.x = excl; o.y = excl + v.x; o.z = o.y + v.y; o.w = o.z + v.z;
    *(int4*)(offs + gi) = o;
}

// scatter edges into CSR-by-dst
__global__ void k_scatter(const int* __restrict__ src, const int* __restrict__ dst,
                          int ecnt_fixed, const int* __restrict__ ecnt_ptr,
                          const int* __restrict__ offs, int* __restrict__ fill,
                          int* __restrict__ csr)
{
    int E = ecnt_ptr ? *ecnt_ptr : ecnt_fixed;
    for (int e = blockIdx.x * blockDim.x + threadIdx.x; e < E;
         e += gridDim.x * blockDim.x) {
        int d = dst[e];
        int p = atomicAdd(&fill[d], 1);
        csr[offs[d] + p] = src[e];
    }
}

// layer-0 node prep: al/ar dots + half copy of x
__global__ void k_nodeprep(const float* __restrict__ x,
                           const float* __restrict__ attl, const float* __restrict__ attr,
                           int n)
{
    int warp = (blockIdx.x * blockDim.x + threadIdx.x) >> 5;
    int lane = threadIdx.x & 31;
    if (warp >= n) return;
    float4 cv = __ldg((const float4*)(x + (size_t)warp * CC) + lane);
    float4 lv = ((const float4*)attl)[lane];
    float4 rv = ((const float4*)attr)[lane];
    float al = cv.x*lv.x + cv.y*lv.y + cv.z*lv.z + cv.w*lv.w;
    float ar = cv.x*rv.x + cv.y*rv.y + cv.z*rv.z + cv.w*rv.w;
#pragma unroll
    for (int o = 16; o; o >>= 1) {
        al += __shfl_xor_sync(0xffffffffu, al, o);
        ar += __shfl_xor_sync(0xffffffffu, ar, o);
    }
    if (lane == 0) { g_al[warp] = al; g_ar[warp] = ar; }
    uint2 h;
    *reinterpret_cast<__half2*>(&h.x) = __floats2half2_rn(cv.x, cv.y);
    *reinterpret_cast<__half2*>(&h.y) = __floats2half2_rn(cv.z, cv.w);
    ((uint2*)(g_xh + (size_t)warp * CC))[lane] = h;
}

// warp per dst: CSR aggregation (half feats) + self loop + EPS + relu + fused pool
__global__ void k_agg(const __half* __restrict__ curh, const int* __restrict__ oidx,
                      const int* __restrict__ deg, const int* __restrict__ offs,
                      const int* __restrict__ csr, int log2npg, int layer)
{
    __shared__ unsigned smax[128];
    int tid  = threadIdx.x;
    int lane = tid & 31;
    if (tid < 128) smax[tid] = 0;
    __syncthreads();

    int d = (blockIdx.x * blockDim.x + tid) >> 5;
    int start = offs[d];
    int cnt   = deg[d];
    float dind = rsqrtf((float)cnt + 1.0f);
    float ald  = g_al[d];

    float4 a = {0.f, 0.f, 0.f, 0.f};
    for (int base = 0; base < cnt; base += 32) {
        int j = base + lane;
        int s = 0; float coef = 0.f;
        if (j < cnt) {
            s = csr[start + j];
            coef = rsqrtf((float)deg[s] + 1.0f) * dind * tanhf(ald + g_ar[s]);
        }
        int m = min(32, cnt - base);
        int t = 0;
        for (; t + 8 <= m; t += 8) {
            uint2 p[8]; float c[8];
#pragma unroll
            for (int q = 0; q < 8; q++) {
                int sq = __shfl_sync(0xffffffffu, s, t + q);
                c[q]   = __shfl_sync(0xffffffffu, coef, t + q);
                p[q]   = __ldg((const uint2*)(curh + (size_t)sq * CC) + lane);
            }
#pragma unroll
            for (int q = 0; q < 8; q++) {
                float2 f0 = h2f(p[q].x), f1 = h2f(p[q].y);
                a.x += c[q]*f0.x; a.y += c[q]*f0.y;
                a.z += c[q]*f1.x; a.w += c[q]*f1.y;
            }
        }
        if (t + 4 <= m) {
            uint2 p[4]; float c[4];
#pragma unroll
            for (int q = 0; q < 4; q++) {
                int sq = __shfl_sync(0xffffffffu, s, t + q);
                c[q]   = __shfl_sync(0xffffffffu, coef, t + q);
                p[q]   = __ldg((const uint2*)(curh + (size_t)sq * CC) + lane);
            }
#pragma unroll
            for (int q = 0; q < 4; q++) {
                float2 f0 = h2f(p[q].x), f1 = h2f(p[q].y);
                a.x += c[q]*f0.x; a.y += c[q]*f0.y;
                a.z += c[q]*f1.x; a.w += c[q]*f1.y;
            }
            t += 4;
        }
        for (; t < m; t++) {
            int   ss = __shfl_sync(0xffffffffu, s, t);
            float cc = __shfl_sync(0xffffffffu, coef, t);
            uint2 p = __ldg((const uint2*)(curh + (size_t)ss * CC) + lane);
            float2 f0 = h2f(p.x), f1 = h2f(p.y);
            a.x += cc*f0.x; a.y += cc*f0.y; a.z += cc*f1.x; a.w += cc*f1.y;
        }
    }

    uint2 pc = __ldg((const uint2*)(curh + (size_t)d * CC) + lane);
    uint2 po = oidx ? __ldg((const uint2*)(g_xh + (size_t)__ldg(&oidx[d]) * CC) + lane)
                    : pc;
    float2 c01 = h2f(pc.x), c23 = h2f(pc.y);
    float2 o01 = h2f(po.x), o23 = h2f(po.y);
    float c0 = dind * dind * tanhf(ald + g_ar[d]);
    a.x = fmaxf(c0*c01.x + EPS_FA*o01.x + a.x, 0.f);
    a.y = fmaxf(c0*c01.y + EPS_FA*o01.y + a.y, 0.f);
    a.z = fmaxf(c0*c23.x + EPS_FA*o23.x + a.z, 0.f);
    a.w = fmaxf(c0*c23.y + EPS_FA*o23.y + a.w, 0.f);
    ((float4*)g_acc)[(size_t)d * 32 + lane] = a;

    atomicMax(&smax[lane*4 + 0], __float_as_uint(a.x));
    atomicMax(&smax[lane*4 + 1], __float_as_uint(a.y));
    atomicMax(&smax[lane*4 + 2], __float_as_uint(a.z));
    atomicMax(&smax[lane*4 + 3], __float_as_uint(a.w));
    __syncthreads();
    if (tid < 128) {
        int g = (int)((blockIdx.x * (blockDim.x >> 5)) >> log2npg);
        atomicMax((unsigned*)&g_pool[(layer * G + g) * CC + tid], smax[tid]);
    }
}

// ---- exact stable top-k via counting rank ----
__global__ void k_rank1(const int* __restrict__ score)
{
    __shared__ int hist[8][SBINS];
    int wid = threadIdx.x >> 5, lane = threadIdx.x & 31;
    int chunk = blockIdx.x * 8 + wid;
    for (int i = lane; i < SBINS; i += 32) hist[wid][i] = 0;
    __syncwarp();
    int base = chunk * 256;
#pragma unroll
    for (int r = 0; r < 8; r++) {
        int i = base + r * 32 + lane;
        int s = min(score[i], SBINS - 1);
        unsigned mask = __match_any_sync(0xffffffffu, s);
        int intra = __popc(mask & ((1u << lane) - 1u));
        int cur = hist[wid][s];
        __syncwarp();
        if (intra == 0) hist[wid][s] = cur + __popc(mask);
        __syncwarp();
        g_seq[i] = cur + intra;
    }
    for (int i = lane; i < SBINS; i += 32) g_chist[chunk * SBINS + i] = hist[wid][i];
}

__global__ void k_rank2(int nch)
{
    __shared__ int tot[SBINS];
    int g = blockIdx.x, s = threadIdx.x;
    int run = 0;
    for (int c = 0; c < nch; c++) {
        int idx = (g * nch + c) * SBINS + s;
        int v = g_chist[idx];
        g_chist[idx] = run;
        run += v;
    }
    tot[s] = run;
    __syncthreads();
    int acc = run;
    for (int off = 1; off < SBINS; off <<= 1) {
        int add = (s + off < SBINS) ? tot[s + off] : 0;
        __syncthreads();
        acc += add;
        tot[s] = acc;
        __syncthreads();
    }
    g_cntgt[g * SBINS + s] = acc - run;
}

__global__ void k_rank3(const int* __restrict__ score, int* __restrict__ perm,
                        int log2npg, int kk)
{
    int i = blockIdx.x * blockDim.x + threadIdx.x;
    int s = min(score[i], SBINS - 1);
    int g = i >> log2npg;
    int chunk = i >> 8;
    int rank = g_cntgt[g * SBINS + s] + g_chist[chunk * SBINS + s] + g_seq[i];
    int nm = -1;
    if (rank < kk) {
        int neu = g * kk + rank;
        perm[neu] = i;
        nm = neu;
    }
    g_nmap[i] = nm;
}

// compact surviving edges + next-layer deg/score
__global__ void k_compactdeg(const int* __restrict__ src, const int* __restrict__ dst,
                             int ecnt_fixed, const int* __restrict__ ecnt_ptr,
                             int* __restrict__ osrc, int* __restrict__ odst,
                             int* __restrict__ cnt,
                             int* __restrict__ degN, int* __restrict__ scoreN)
{
    int E = ecnt_ptr ? *ecnt_ptr : ecnt_fixed;
    int lane   = threadIdx.x & 31;
    int warp   = (blockIdx.x * blockDim.x + threadIdx.x) >> 5;
    int nwarps = (gridDim.x * blockDim.x) >> 5;
    for (int base = warp * 32; base < E; base += nwarps * 32) {
        int e = base + lane;
        bool keep = false; int ns = 0, nd = 0;
        if (e < E) {
            ns = g_nmap[src[e]];
            nd = g_nmap[dst[e]];
            keep = (ns >= 0) && (nd >= 0);
        }
        unsigned bal = __ballot_sync(0xffffffffu, keep);
        int tot = __popc(bal);
        int pos = 0;
        if (lane == 0 && tot) pos = atomicAdd(cnt, tot);
        pos = __shfl_sync(0xffffffffu, pos, 0);
        if (keep) {
            int off = __popc(bal & ((1u << lane) - 1u));
            osrc[pos + off] = ns;
            odst[pos + off] = nd;
            atomicAdd(&degN[nd], 1);
            if (scoreN) atomicAdd(&scoreN[ns], 1);
        }
    }
}

// gather kept features (fp32 h -> half cur) + next al/ar + orig-index composition
__global__ void k_gatherprep(const float* __restrict__ h, __half* __restrict__ cur_out,
                             const int* __restrict__ oidx_old, int* __restrict__ oidx_new,
                             const int* __restrict__ perm,
                             const float* __restrict__ attl, const float* __restrict__ attr,
                             int cnt)
{
    int warp = (blockIdx.x * blockDim.x + threadIdx.x) >> 5;
    int lane = threadIdx.x & 31;
    if (warp >= cnt) return;
    int old = perm[warp];
    float4 v = __ldg((const float4*)(h + (size_t)old * CC) + lane);
    uint2 hh;
    *reinterpret_cast<__half2*>(&hh.x) = __floats2half2_rn(v.x, v.y);
    *reinterpret_cast<__half2*>(&hh.y) = __floats2half2_rn(v.z, v.w);
    ((uint2*)(cur_out + (size_t)warp * CC))[lane] = hh;
    float4 lv = ((const float4*)attl)[lane];
    float4 rv = ((const float4*)attr)[lane];
    float al = v.x*lv.x + v.y*lv.y + v.z*lv.z + v.w*lv.w;
    float ar = v.x*rv.x + v.y*rv.y + v.z*rv.z + v.w*rv.w;
#pragma unroll
    for (int o = 16; o; o >>= 1) {
        al += __shfl_xor_sync(0xffffffffu, al, o);
        ar += __shfl_xor_sync(0xffffffffu, ar, o);
    }
    if (lane == 0) {
        g_al[warp] = al;
        g_ar[warp] = ar;
        oidx_new[warp] = oidx_old ? oidx_old[old] : old;
    }
}

// GRU (h0=0) + final linears + root residual
__global__ void k_head(const float* __restrict__ w_ih, const float* __restrict__ b_ih,
                       const float* __restrict__ b_hh,
                       const float* __restrict__ w_fin, const float* __restrict__ b_fin,
                       const float* __restrict__ w_root, const float* __restrict__ b_root,
                       const float* __restrict__ root, const float* __restrict__ alpha_p,
                       float* __restrict__ out)
{
    __shared__ float fused[LL * CC];
    __shared__ float hgru[HH];
    __shared__ float rootv[CC];
    int g = blockIdx.x, t = threadIdx.x;
    for (int i = t; i < LL * CC; i += 256) {
        int layer = i >> 7, c = i & 127;
        fused[i] = g_pool[layer * G * CC + g * CC + c];
    }
    if (t < CC) rootv[t] = root[g * CC + t];
    __syncthreads();

    float gr = b_ih[t], gz = b_ih[HH + t], gn = b_ih[2 * HH + t];
    const float* wr = w_ih + (size_t)t            * (LL * CC);
    const float* wz = w_ih + (size_t)(HH + t)     * (LL * CC);
    const float* wn = w_ih + (size_t)(2 * HH + t) * (LL * CC);
    for (int j = 0; j < LL * CC; j++) {
        float f = fused[j];
        gr += wr[j] * f; gz += wz[j] * f; gn += wn[j] * f;
    }
    float r  = 1.0f / (1.0f + expf(-(gr + b_hh[t])));
    float z  = 1.0f / (1.0f + expf(-(gz + b_hh[HH + t])));
    float nc = tanhf(gn + r * b_hh[2 * HH + t]);
    hgru[t] = (1.0f - z) * nc;
    __syncthreads();

    if (t < CC) {
        float acc = b_fin[t];
        const float* wf = w_fin + (size_t)t * HH;
        for (int j = 0; j < HH; j++) acc += wf[j] * hgru[j];
        float re = b_root[t];
        const float* wo = w_root + (size_t)t * CC;
        for (int j = 0; j < CC; j++) re += wo[j] * rootv[j];
        float a = *alpha_p;
        out[g * CC + t] = a * acc + (1.0f - a) * re;
    }
}

// ---------------- launch ----------------

extern "C" void kernel_launch(void* const* d_in, const int* in_sizes, int n_in,
                              void* d_out, int out_size)
{
    const float* x      = (const float*)d_in[0];
    const int*   ei     = (const int*)  d_in[1];
    const float* root   = (const float*)d_in[3];
    const float* att_l  = (const float*)d_in[4];
    const float* att_r  = (const float*)d_in[5];
    const float* w_ih   = (const float*)d_in[6];
    const float* b_ih   = (const float*)d_in[8];
    const float* b_hh   = (const float*)d_in[9];
    const float* w_fin  = (const float*)d_in[10];
    const float* b_fin  = (const float*)d_in[11];
    const float* w_root = (const float*)d_in[12];
    const float* b_root = (const float*)d_in[13];
    const float* alpha  = (const float*)d_in[14];
    float* out = (float*)d_out;

    int E = in_sizes[1] / 2;
    const int* src0 = ei;
    const int* dst0 = ei + E;

    float *acc;
    __half *xh, *curh;
    int *srcA, *dstA, *srcB, *dstB, *cnt, *oidxA, *oidxB;
    int *deg0, *deg1, *deg2, *scoreA, *scoreB;
    int *fill0, *fill1, *fill2, *offs0, *offs1, *offs2;
    int *csr0, *csr1, *csr2, *permA, *permB;
    unsigned *st0, *st1, *st2;
    cudaGetSymbolAddress((void**)&acc,    g_acc);
    cudaGetSymbolAddress((void**)&xh,     g_xh);
    cudaGetSymbolAddress((void**)&curh,   g_curh);
    cudaGetSymbolAddress((void**)&srcA,   g_srcA);
    cudaGetSymbolAddress((void**)&dstA,   g_dstA);
    cudaGetSymbolAddress((void**)&srcB,   g_srcB);
    cudaGetSymbolAddress((void**)&dstB,   g_dstB);
    cudaGetSymbolAddress((void**)&cnt,    g_cnt);
    cudaGetSymbolAddress((void**)&oidxA,  g_oidxA);
    cudaGetSymbolAddress((void**)&oidxB,  g_oidxB);
    cudaGetSymbolAddress((void**)&deg0,   g_deg0);
    cudaGetSymbolAddress((void**)&deg1,   g_deg1);
    cudaGetSymbolAddress((void**)&deg2,   g_deg2);
    cudaGetSymbolAddress((void**)&scoreA, g_scoreA);
    cudaGetSymbolAddress((void**)&scoreB, g_scoreB);
    cudaGetSymbolAddress((void**)&fill0,  g_fill0);
    cudaGetSymbolAddress((void**)&fill1,  g_fill1);
    cudaGetSymbolAddress((void**)&fill2,  g_fill2);
    cudaGetSymbolAddress((void**)&offs0,  g_offs0);
    cudaGetSymbolAddress((void**)&offs1,  g_offs1);
    cudaGetSymbolAddress((void**)&offs2,  g_offs2);
    cudaGetSymbolAddress((void**)&csr0,   g_csr0);
    cudaGetSymbolAddress((void**)&csr1,   g_csr1);
    cudaGetSymbolAddress((void**)&csr2,   g_csr2);
    cudaGetSymbolAddress((void**)&permA,  g_permA);
    cudaGetSymbolAddress((void**)&permB,  g_permB);
    cudaGetSymbolAddress((void**)&st0,    g_state0);
    cudaGetSymbolAddress((void**)&st1,    g_state1);
    cudaGetSymbolAddress((void**)&st2,    g_state2);

    static cudaStream_t sA = nullptr, sB = nullptr;
    static cudaEvent_t e0, eNP, eDeg, eR30, eS1, eR31, eS2;
    if (!sA) {
        cudaStreamCreateWithFlags(&sA, cudaStreamNonBlocking);
        cudaStreamCreateWithFlags(&sB, cudaStreamNonBlocking);
        cudaEventCreateWithFlags(&e0,   cudaEventDisableTiming);
        cudaEventCreateWithFlags(&eNP,  cudaEventDisableTiming);
        cudaEventCreateWithFlags(&eDeg, cudaEventDisableTiming);
        cudaEventCreateWithFlags(&eR30, cudaEventDisableTiming);
        cudaEventCreateWithFlags(&eS1,  cudaEventDisableTiming);
        cudaEventCreateWithFlags(&eR31, cudaEventDisableTiming);
        cudaEventCreateWithFlags(&eS2,  cudaEventDisableTiming);
    }

    // ---- main stream: zero + degree ----
    k_zero  <<<512, 256>>>();
    cudaEventRecord(e0, 0);
    cudaStreamWaitEvent(sA, e0, 0);
    k_nodeprep<<<131072 / 8, 256, 0, sA>>>(x, att_l, att_r, 131072);
    cudaEventRecord(eNP, sA);

    k_degree<<<1024, 256>>>(src0, dst0, E);
    cudaEventRecord(eDeg, 0);

    // ---- stream B: rank/compact/scan/scatter pipeline (layers 1,2 bookkeeping) ----
    cudaStreamWaitEvent(sB, eDeg, 0);
    k_rank1<<<64, 256, 0, sB>>>(scoreA);
    k_rank2<<<G, SBINS, 0, sB>>>(64);
    k_rank3<<<512, 256, 0, sB>>>(scoreA, permA, 14, 8192);
    cudaEventRecord(eR30, sB);
    k_compactdeg<<<1024, 256, 0, sB>>>(src0, dst0, E, nullptr,
                                       srcA, dstA, cnt + 0, deg1, scoreB);
    k_scan   <<<16, 1024, 0, sB>>>(deg1, offs1, st1);
    k_scatter<<<1024, 256, 0, sB>>>(srcA, dstA, 0, cnt + 0, offs1, fill1, csr1);
    cudaEventRecord(eS1, sB);
    k_rank1<<<32, 256, 0, sB>>>(scoreB);
    k_rank2<<<G, SBINS, 0, sB>>>(32);
    k_rank3<<<256, 256, 0, sB>>>(scoreB, permB, 13, 4096);
    cudaEventRecord(eR31, sB);
    k_compactdeg<<<1024, 256, 0, sB>>>(srcA, dstA, 0, cnt + 0,
                                       srcB, dstB, cnt + 1, deg2, nullptr);
    k_scan   <<<8, 1024, 0, sB>>>(deg2, offs2, st2);
    k_scatter<<<1024, 256, 0, sB>>>(srcB, dstB, 0, cnt + 1, offs2, fill2, csr2);
    cudaEventRecord(eS2, sB);

    // ---- main stream: feature pipeline ----
    k_scan   <<<32, 1024>>>(deg0, offs0, st0);
    k_scatter<<<1024, 256>>>(src0, dst0, E, nullptr, offs0, fill0, csr0);
    cudaStreamWaitEvent(0, eNP, 0);
    k_agg<<<131072 / 8, 256>>>(xh, nullptr, deg0, offs0, csr0, 14, 0);
    cudaStreamWaitEvent(0, eR30, 0);
    k_gatherprep<<<65536 / 8, 256>>>(acc, curh, nullptr, oidxA, permA,
                                     att_l + CC, att_r + CC, 65536);
    cudaStreamWaitEvent(0, eS1, 0);
    k_agg<<<65536 / 8, 256>>>(curh, oidxA, deg1, offs1, csr1, 13, 1);
    cudaStreamWaitEvent(0, eR31, 0);
    k_gatherprep<<<32768 / 8, 256>>>(acc, curh, oidxA, oidxB, permB,
                                     att_l + 2 * CC, att_r + 2 * CC, 32768);
    cudaStreamWaitEvent(0, eS2, 0);
    k_agg<<<32768 / 8, 256>>>(curh, oidxB, deg2, offs2, csr2, 12, 2);

    // ---- head ----
    k_head<<<G, 256>>>(w_ih, b_ih, b_hh, w_fin, b_fin, w_root, b_root,
                       root, alpha, out);
}

// round 8
// speedup vs baseline: 1.7199x; 1.0985x over previous
#include <cuda_runtime.h>
#include <cuda_fp16.h>

#define G       8
#define CC      128
#define LL      3
#define HH      256
#define EPS_FA  0.1f
#define EMAX    1048576
#define SBINS   512

// ---------------- scratch (device globals; no allocations) ----------------
__device__ __half g_xh [131072 * CC];          // half copy of original x
__device__ __half g_h0 [131072 * CC];          // layer-0 output h (half), orig-id indexed
__device__ __half g_h1 [65536 * CC];           // layer-1 output h (half), layer1-id indexed
__device__ int    g_csr0[EMAX];
__device__ __align__(16) int g_deg0[131072];
__device__ int    g_scoreA[131072], g_scoreB[65536];
__device__ int    g_fill0[131072];
__device__ __align__(16) int g_offs0[131072];
__device__ unsigned g_state0[64];
__device__ int    g_deg1o[131072];             // layer-1 in-degree, indexed by ORIG id
__device__ int    g_deg2o[65536];              // layer-2 in-degree, indexed by LAYER-1 id
__device__ int    g_nmapA[131072], g_nmapB[65536];
__device__ int    g_permA[65536], g_permB[32768];
__device__ float  g_al0[131072], g_ar0[131072];
__device__ float  g_al1[131072], g_ar1[131072]; // indexed by orig id
__device__ float  g_al2[65536],  g_ar2[65536];  // indexed by layer-1 id
__device__ float  g_pool[LL * G * CC];

__device__ __forceinline__ float2 h2f(unsigned u)
{
    __half2 h = *reinterpret_cast<__half2*>(&u);
    return __half22float2(h);
}

// ---------------- kernels ----------------

__global__ void k_zero()
{
    int i = blockIdx.x * blockDim.x + threadIdx.x;   // 131072 threads
    g_deg0[i] = 0; g_fill0[i] = 0; g_scoreA[i] = 0;
    if (i < 65536) g_scoreB[i] = 0;
    if (i < LL * G * CC) g_pool[i] = 0.0f;
    if (i < 64) g_state0[i] = 0u;
}

__global__ void k_degree(const int* __restrict__ src, const int* __restrict__ dst, int E)
{
    for (int e = blockIdx.x * blockDim.x + threadIdx.x; e < E;
         e += gridDim.x * blockDim.x) {
        atomicAdd(&g_deg0[dst[e]], 1);
        atomicAdd(&g_scoreA[src[e]], 1);
    }
}

// single-pass exclusive scan of deg0, 4 items/thread, warp-parallel lookback
__global__ void __launch_bounds__(1024, 1) k_scan()
{
    __shared__ int sh[1024];
    __shared__ int s_base;
    int tid = threadIdx.x, b = blockIdx.x;
    int gi = b * 4096 + tid * 4;
    int4 v = *(const int4*)(g_deg0 + gi);
    int tsum = v.x + v.y + v.z + v.w;
    sh[tid] = tsum;
    __syncthreads();
    int acc = tsum;
#pragma unroll
    for (int off = 1; off < 1024; off <<= 1) {
        int add = (tid >= off) ? sh[tid - off] : 0;
        __syncthreads();
        acc += add;
        sh[tid] = acc;
        __syncthreads();
    }
    int total = sh[1023];
    if (tid == 0 && b > 0)
        atomicExch(&g_state0[b], 0x40000000u | (unsigned)total);
    if (tid < 32) {
        int base = 0;
        if (b > 0) {
            int idx = b - 1 - tid;
            while (true) {
                unsigned s = 0;
                if (idx >= 0) { do { s = atomicAdd(&g_state0[idx], 0u); } while (s == 0u); }
                unsigned pm = __ballot_sync(0xffffffffu, idx >= 0 && (s & 0x80000000u));
                int firstP = pm ? (__ffs(pm) - 1) : 32;
                int c = (idx >= 0 && tid <= firstP) ? (int)(s & 0x3FFFFFFFu) : 0;
#pragma unroll
                for (int o = 16; o; o >>= 1) c += __shfl_xor_sync(0xffffffffu, c, o);
                base += c;
                if (pm) break;
                idx -= 32;
            }
        }
        if (tid == 0) {
            atomicExch(&g_state0[b], 0x80000000u | (unsigned)(base + total));
            s_base = base;
        }
    }
    __syncthreads();
    int excl = s_base + acc - tsum;
    int4 o;
    o.x = excl; o.y = excl + v.x; o.z = o.y + v.y; o.w = o.z + v.z;
    *(int4*)(g_offs0 + gi) = o;
}

__global__ void k_scatter(const int* __restrict__ src, const int* __restrict__ dst, int E)
{
    for (int e = blockIdx.x * blockDim.x + threadIdx.x; e < E;
         e += gridDim.x * blockDim.x) {
        int d = dst[e];
        int p = atomicAdd(&g_fill0[d], 1);
        g_csr0[g_offs0[d] + p] = src[e];
    }
}

// layer-0 node prep: al/ar dots + half copy of x
__global__ void k_nodeprep(const float* __restrict__ x,
                           const float* __restrict__ attl, const float* __restrict__ attr)
{
    int warp = (blockIdx.x * blockDim.x + threadIdx.x) >> 5;
    int lane = threadIdx.x & 31;
    float4 cv = __ldg((const float4*)(x + (size_t)warp * CC) + lane);
    float4 lv = ((const float4*)attl)[lane];
    float4 rv = ((const float4*)attr)[lane];
    float al = cv.x*lv.x + cv.y*lv.y + cv.z*lv.z + cv.w*lv.w;
    float ar = cv.x*rv.x + cv.y*rv.y + cv.z*rv.z + cv.w*rv.w;
#pragma unroll
    for (int o = 16; o; o >>= 1) {
        al += __shfl_xor_sync(0xffffffffu, al, o);
        ar += __shfl_xor_sync(0xffffffffu, ar, o);
    }
    if (lane == 0) { g_al0[warp] = al; g_ar0[warp] = ar; }
    uint2 h;
    *reinterpret_cast<__half2*>(&h.x) = __floats2half2_rn(cv.x, cv.y);
    *reinterpret_cast<__half2*>(&h.y) = __floats2half2_rn(cv.z, cv.w);
    ((uint2*)(g_xh + (size_t)warp * CC))[lane] = h;
}

// unified aggregation: warp per dst node, masked walk of the ORIGINAL csr0 list.
template<int MODE>
__global__ void __launch_bounds__(256) k_agg(
                      const __half* __restrict__ feat,
                      const float* __restrict__ alC, const float* __restrict__ arC,
                      const int* __restrict__ degC,
                      float* __restrict__ alN, float* __restrict__ arN,
                      const float* __restrict__ attlN, const float* __restrict__ attrN,
                      __half* __restrict__ hout, int log2npg, int layer)
{
    __shared__ unsigned smax[128];
    int tid  = threadIdx.x;
    int lane = tid & 31;
    if (tid < 128) smax[tid] = 0;
    __syncthreads();

    int d = (blockIdx.x * blockDim.x + tid) >> 5;
    int old0, selfIdx;
    if (MODE == 0)      { old0 = d; selfIdx = d; }
    else if (MODE == 1) { old0 = g_permA[d]; selfIdx = old0; }
    else                { int old1 = g_permB[d]; selfIdx = old1; old0 = g_permA[old1]; }

    int start = g_offs0[old0];
    int cnt   = g_deg0[old0];
    int ddeg  = (MODE == 0) ? cnt : degC[selfIdx];
    float dind = rsqrtf((float)ddeg + 1.0f);
    float ald  = alC[selfIdx];

    float4 a = {0.f, 0.f, 0.f, 0.f};
    for (int base = 0; base < cnt; base += 32) {
        int j = base + lane;
        bool valid = false; int fidx = 0; float coef = 0.f;
        if (j < cnt) {
            int s0 = g_csr0[start + j];
            if (MODE == 0) { fidx = s0; valid = true; }
            else if (MODE == 1) { fidx = s0; valid = (g_nmapA[s0] >= 0); }
            else {
                int s1 = g_nmapA[s0];
                if (s1 >= 0 && g_nmapB[s1] >= 0) { valid = true; fidx = s1; }
            }
        }
        if (valid)
            coef = rsqrtf((float)degC[fidx] + 1.0f) * dind * tanhf(ald + arC[fidx]);
        unsigned bal = __ballot_sync(0xffffffffu, valid);
        int m = __popc(bal);
        int t = 0;
        for (; t + 8 <= m; t += 8) {
            uint2 p[8]; float c[8];
#pragma unroll
            for (int q = 0; q < 8; q++) {
                int l = __fns(bal, 0, t + q + 1);
                c[q]  = __shfl_sync(0xffffffffu, coef, l);
                int f = __shfl_sync(0xffffffffu, fidx, l);
                p[q]  = __ldg((const uint2*)(feat + (size_t)f * CC) + lane);
            }
#pragma unroll
            for (int q = 0; q < 8; q++) {
                float2 f0 = h2f(p[q].x), f1 = h2f(p[q].y);
                a.x += c[q]*f0.x; a.y += c[q]*f0.y;
                a.z += c[q]*f1.x; a.w += c[q]*f1.y;
            }
        }
        if (t + 4 <= m) {
            uint2 p[4]; float c[4];
#pragma unroll
            for (int q = 0; q < 4; q++) {
                int l = __fns(bal, 0, t + q + 1);
                c[q]  = __shfl_sync(0xffffffffu, coef, l);
                int f = __shfl_sync(0xffffffffu, fidx, l);
                p[q]  = __ldg((const uint2*)(feat + (size_t)f * CC) + lane);
            }
#pragma unroll
            for (int q = 0; q < 4; q++) {
                float2 f0 = h2f(p[q].x), f1 = h2f(p[q].y);
                a.x += c[q]*f0.x; a.y += c[q]*f0.y;
                a.z += c[q]*f1.x; a.w += c[q]*f1.y;
            }
            t += 4;
        }
        for (; t < m; t++) {
            int l = __fns(bal, 0, t + 1);
            float cc = __shfl_sync(0xffffffffu, coef, l);
            int f = __shfl_sync(0xffffffffu, fidx, l);
            uint2 p = __ldg((const uint2*)(feat + (size_t)f * CC) + lane);
            float2 f0 = h2f(p.x), f1 = h2f(p.y);
            a.x += cc*f0.x; a.y += cc*f0.y; a.z += cc*f1.x; a.w += cc*f1.y;
        }
    }

    // self-loop + EPS*orig + relu
    uint2 pc = __ldg((const uint2*)(feat + (size_t)selfIdx * CC) + lane);
    uint2 po = (MODE == 0) ? pc
             : __ldg((const uint2*)(g_xh + (size_t)old0 * CC) + lane);
    float2 c01 = h2f(pc.x), c23 = h2f(pc.y);
    float2 o01 = h2f(po.x), o23 = h2f(po.y);
    float c0 = dind * dind * tanhf(ald + arC[selfIdx]);
    a.x = fmaxf(c0*c01.x + EPS_FA*o01.x + a.x, 0.f);
    a.y = fmaxf(c0*c01.y + EPS_FA*o01.y + a.y, 0.f);
    a.z = fmaxf(c0*c23.x + EPS_FA*o23.x + a.z, 0.f);
    a.w = fmaxf(c0*c23.y + EPS_FA*o23.y + a.w, 0.f);

    if (MODE < 2) {
        uint2 hh;
        *reinterpret_cast<__half2*>(&hh.x) = __floats2half2_rn(a.x, a.y);
        *reinterpret_cast<__half2*>(&hh.y) = __floats2half2_rn(a.z, a.w);
        ((uint2*)(hout + (size_t)d * CC))[lane] = hh;
        float4 lv = ((const float4*)attlN)[lane];
        float4 rv = ((const float4*)attrN)[lane];
        float aln = a.x*lv.x + a.y*lv.y + a.z*lv.z + a.w*lv.w;
        float arn = a.x*rv.x + a.y*rv.y + a.z*rv.z + a.w*rv.w;
#pragma unroll
        for (int o = 16; o; o >>= 1) {
            aln += __shfl_xor_sync(0xffffffffu, aln, o);
            arn += __shfl_xor_sync(0xffffffffu, arn, o);
        }
        if (lane == 0) { alN[d] = aln; arN[d] = arn; }
    }

    atomicMax(&smax[lane*4 + 0], __float_as_uint(a.x));
    atomicMax(&smax[lane*4 + 1], __float_as_uint(a.y));
    atomicMax(&smax[lane*4 + 2], __float_as_uint(a.z));
    atomicMax(&smax[lane*4 + 3], __float_as_uint(a.w));
    __syncthreads();
    if (tid < 128) {
        int g = (int)((blockIdx.x * (blockDim.x >> 5)) >> log2npg);
        atomicMax((unsigned*)&g_pool[(layer * G + g) * CC + tid], smax[tid]);
    }
}

// fused exact stable top-k (counting rank), one block per graph, 1024 threads.
template<int ROUNDS>
__global__ void __launch_bounds__(1024, 1) k_rank(
                       const int* __restrict__ score, int* __restrict__ perm,
                       int* __restrict__ nmap, int kk)
{
    extern __shared__ int smem[];
    int* whist = smem;              // 32*512
    int* s_tot = smem + 32*512;     // 512
    int* s_cnt = s_tot + 512;       // 512
    int tid = threadIdx.x, w = tid >> 5, lane = tid & 31;
    int npg = ROUNDS * 1024;
    int nbase = blockIdx.x * npg + w * (ROUNDS * 32);

    for (int i = lane; i < 512; i += 32) whist[w*512 + i] = 0;
    __syncwarp();

    int seq[ROUNDS];
#pragma unroll
    for (int r = 0; r < ROUNDS; r++) {
        int i = nbase + r * 32 + lane;
        int s = min(score[i], SBINS - 1);
        unsigned mk = __match_any_sync(0xffffffffu, s);
        int intra = __popc(mk & ((1u << lane) - 1u));
        int cur = whist[w*512 + s];
        __syncwarp();
        if (intra == 0) whist[w*512 + s] = cur + __popc(mk);
        __syncwarp();
        seq[r] = cur + intra;
    }
    __syncthreads();

    if (tid < 512) {
        int run = 0;
        for (int ww = 0; ww < 32; ww++) {
            int v = whist[ww*512 + tid];
            whist[ww*512 + tid] = run;
            run += v;
        }
        s_tot[tid] = run;
        s_cnt[tid] = run;
    }
    __syncthreads();
    for (int off = 1; off < 512; off <<= 1) {
        int add = 0;
        if (tid < 512 && tid + off < 512) add = s_cnt[tid + off];
        __syncthreads();
        if (tid < 512) s_cnt[tid] += add;
        __syncthreads();
    }

#pragma unroll
    for (int r = 0; r < ROUNDS; r++) {
        int i = nbase + r * 32 + lane;
        int s = min(score[i], SBINS - 1);
        int rank = (s_cnt[s] - s_tot[s]) + whist[w*512 + s] + seq[r];
        int nm = -1;
        if (rank < kk) {
            int neu = blockIdx.x * kk + rank;
            perm[neu] = i;
            nm = neu;
        }
        nmap[i] = nm;
    }
}

// layer-1 masked degree + out-degree score
__global__ void k_degscore1()
{
    int j = blockIdx.x * blockDim.x + threadIdx.x;   // 0..65535
    int old0 = g_permA[j];
    int st = g_offs0[old0], c = g_deg0[old0];
    int dcur = 0;
    for (int k = 0; k < c; k++) {
        int s0 = g_csr0[st + k];
        int s1 = g_nmapA[s0];
        if (s1 >= 0) { dcur++; atomicAdd(&g_scoreB[s1], 1); }
    }
    g_deg1o[old0] = dcur;
}

// layer-2 masked degree
__global__ void k_degscore2()
{
    int m = blockIdx.x * blockDim.x + threadIdx.x;   // 0..32767
    int old1 = g_permB[m];
    int old0 = g_permA[old1];
    int st = g_offs0[old0], c = g_deg0[old0];
    int dcur = 0;
    for (int k = 0; k < c; k++) {
        int s0 = g_csr0[st + k];
        int s1 = g_nmapA[s0];
        if (s1 >= 0 && g_nmapB[s1] >= 0) dcur++;
    }
    g_deg2o[old1] = dcur;
}

// GRU (h0=0) + final linears + root residual
__global__ void k_head(const float* __restrict__ w_ih, const float* __restrict__ b_ih,
                       const float* __restrict__ b_hh,
                       const float* __restrict__ w_fin, const float* __restrict__ b_fin,
                       const float* __restrict__ w_root, const float* __restrict__ b_root,
                       const float* __restrict__ root, const float* __restrict__ alpha_p,
                       float* __restrict__ out)
{
    __shared__ float fused[LL * CC];
    __shared__ float hgru[HH];
    __shared__ float rootv[CC];
    int g = blockIdx.x, t = threadIdx.x;
    for (int i = t; i < LL * CC; i += 256) {
        int layer = i >> 7, c = i & 127;
        fused[i] = g_pool[layer * G * CC + g * CC + c];
    }
    if (t < CC) rootv[t] = root[g * CC + t];
    __syncthreads();

    float gr = b_ih[t], gz = b_ih[HH + t], gn = b_ih[2 * HH + t];
    const float* wr = w_ih + (size_t)t            * (LL * CC);
    const float* wz = w_ih + (size_t)(HH + t)     * (LL * CC);
    const float* wn = w_ih + (size_t)(2 * HH + t) * (LL * CC);
    for (int j = 0; j < LL * CC; j++) {
        float f = fused[j];
        gr += wr[j] * f; gz += wz[j] * f; gn += wn[j] * f;
    }
    float r  = 1.0f / (1.0f + expf(-(gr + b_hh[t])));
    float z  = 1.0f / (1.0f + expf(-(gz + b_hh[HH + t])));
    float nc = tanhf(gn + r * b_hh[2 * HH + t]);
    hgru[t] = (1.0f - z) * nc;
    __syncthreads();

    if (t < CC) {
        float acc = b_fin[t];
        const float* wf = w_fin + (size_t)t * HH;
        for (int j = 0; j < HH; j++) acc += wf[j] * hgru[j];
        float re = b_root[t];
        const float* wo = w_root + (size_t)t * CC;
        for (int j = 0; j < CC; j++) re += wo[j] * rootv[j];
        float a = *alpha_p;
        out[g * CC + t] = a * acc + (1.0f - a) * re;
    }
}

// ---------------- launch ----------------

extern "C" void kernel_launch(void* const* d_in, const int* in_sizes, int n_in,
                              void* d_out, int out_size)
{
    const float* x      = (const float*)d_in[0];
    const int*   ei     = (const int*)  d_in[1];
    const float* root   = (const float*)d_in[3];
    const float* att_l  = (const float*)d_in[4];
    const float* att_r  = (const float*)d_in[5];
    const float* w_ih   = (const float*)d_in[6];
    const float* b_ih   = (const float*)d_in[8];
    const float* b_hh   = (const float*)d_in[9];
    const float* w_fin  = (const float*)d_in[10];
    const float* b_fin  = (const float*)d_in[11];
    const float* w_root = (const float*)d_in[12];
    const float* b_root = (const float*)d_in[13];
    const float* alpha  = (const float*)d_in[14];
    float* out = (float*)d_out;

    int E = in_sizes[1] / 2;
    const int* src0 = ei;
    const int* dst0 = ei + E;

    __half *xh, *h0, *h1;
    int *scoreA, *scoreB, *permA, *permB, *nmapA, *nmapB, *deg0, *deg1o, *deg2o;
    float *al0, *ar0, *al1, *ar1, *al2, *ar2;
    cudaGetSymbolAddress((void**)&xh,     g_xh);
    cudaGetSymbolAddress((void**)&h0,     g_h0);
    cudaGetSymbolAddress((void**)&h1,     g_h1);
    cudaGetSymbolAddress((void**)&scoreA, g_scoreA);
    cudaGetSymbolAddress((void**)&scoreB, g_scoreB);
    cudaGetSymbolAddress((void**)&permA,  g_permA);
    cudaGetSymbolAddress((void**)&permB,  g_permB);
    cudaGetSymbolAddress((void**)&nmapA,  g_nmapA);
    cudaGetSymbolAddress((void**)&nmapB,  g_nmapB);
    cudaGetSymbolAddress((void**)&deg0,   g_deg0);
    cudaGetSymbolAddress((void**)&deg1o,  g_deg1o);
    cudaGetSymbolAddress((void**)&deg2o,  g_deg2o);
    cudaGetSymbolAddress((void**)&al0,    g_al0);
    cudaGetSymbolAddress((void**)&ar0,    g_ar0);
    cudaGetSymbolAddress((void**)&al1,    g_al1);
    cudaGetSymbolAddress((void**)&ar1,    g_ar1);
    cudaGetSymbolAddress((void**)&al2,    g_al2);
    cudaGetSymbolAddress((void**)&ar2,    g_ar2);

    static cudaStream_t sA = nullptr, sB = nullptr;
    static cudaEvent_t e0, eNP, eDeg, eScat, eDS1, eDS2;
    if (!sA) {
        cudaStreamCreateWithFlags(&sA, cudaStreamNonBlocking);
        cudaStreamCreateWithFlags(&sB, cudaStreamNonBlocking);
        cudaEventCreateWithFlags(&e0,    cudaEventDisableTiming);
        cudaEventCreateWithFlags(&eNP,   cudaEventDisableTiming);
        cudaEventCreateWithFlags(&eDeg,  cudaEventDisableTiming);
        cudaEventCreateWithFlags(&eScat, cudaEventDisableTiming);
        cudaEventCreateWithFlags(&eDS1,  cudaEventDisableTiming);
        cudaEventCreateWithFlags(&eDS2,  cudaEventDisableTiming);
        cudaFuncSetAttribute(k_rank<16>, cudaFuncAttributeMaxDynamicSharedMemorySize, 70656);
        cudaFuncSetAttribute(k_rank<8>,  cudaFuncAttributeMaxDynamicSharedMemorySize, 70656);
    }
    const int RSMEM = (32*512 + 1024) * 4;

    // ---- fork side stream A from the capture stream FIRST (capture rule) ----
    k_zero<<<512, 256>>>();
    cudaEventRecord(e0, 0);
    cudaStreamWaitEvent(sA, e0, 0);
    k_nodeprep<<<131072 / 8, 256, 0, sA>>>(x, att_l, att_r);
    cudaEventRecord(eNP, sA);

    // main: degree -> scan -> scatter
    k_degree <<<1024, 256>>>(src0, dst0, E);
    cudaEventRecord(eDeg, 0);
    k_scan   <<<32, 1024>>>();
    k_scatter<<<1024, 256>>>(src0, dst0, E);
    cudaEventRecord(eScat, 0);

    // side stream B (forked via eDeg): rank + masked degrees, hidden under agg0/agg1
    cudaStreamWaitEvent(sB, eDeg, 0);
    k_rank<16><<<G, 1024, RSMEM, sB>>>(scoreA, permA, nmapA, 8192);
    cudaStreamWaitEvent(sB, eScat, 0);
    k_degscore1<<<256, 256, 0, sB>>>();
    cudaEventRecord(eDS1, sB);
    k_rank<8><<<G, 1024, RSMEM, sB>>>(scoreB, permB, nmapB, 4096);
    k_degscore2<<<128, 256, 0, sB>>>();
    cudaEventRecord(eDS2, sB);

    // main: aggregation chain
    cudaStreamWaitEvent(0, eNP, 0);
    k_agg<0><<<16384, 256>>>(xh, al0, ar0, deg0,
                             al1, ar1, att_l + CC, att_r + CC, h0, 14, 0);
    cudaStreamWaitEvent(0, eDS1, 0);
    k_agg<1><<<8192, 256>>>(h0, al1, ar1, deg1o,
                            al2, ar2, att_l + 2*CC, att_r + 2*CC, h1, 13, 1);
    cudaStreamWaitEvent(0, eDS2, 0);
    k_agg<2><<<4096, 256>>>(h1, al2, ar2, deg2o,
                            nullptr, nullptr, nullptr, nullptr, nullptr, 12, 2);

    k_head<<<G, 256>>>(w_ih, b_ih, b_hh, w_fin, b_fin, w_root, b_root,
                       root, alpha, out);
}

// round 9
// speedup vs baseline: 1.9042x; 1.1072x over previous
#include <cuda_runtime.h>
#include <cuda_fp16.h>

#define G       8
#define CC      128
#define LL      3
#define HH      256
#define EPS_FA  0.1f
#define EMAX    1048576
#define SBINS   512

// ---------------- scratch (device globals; no allocations) ----------------
__device__ __half  g_xh [131072 * CC];         // half copy of original x
__device__ __half  g_h0 [131072 * CC];         // layer-0 h (half), orig-id indexed
__device__ __half  g_h1 [131072 * CC];         // layer-1 h (half), orig-id indexed
__device__ int     g_csr0[EMAX];
__device__ __align__(16) int g_deg0[131072];
__device__ int     g_scoreA[131072], g_scoreB[65536];
__device__ int     g_fill0[131072];
__device__ __align__(16) int g_offs0[131072];
__device__ unsigned g_state0[64];
__device__ int     g_nmapA[131072], g_nmapB[65536];
__device__ int     g_permA[65536], g_permB[32768];
__device__ float2  g_pack0[131072];            // {ar0, dinv0}
__device__ float2  g_pack1[131072];            // {ar1, dinv1 or 0 if dropped}
__device__ float2  g_pack2[131072];            // {ar2, dinv2 or 0 if dropped}
__device__ float   g_al0[131072], g_al1[131072], g_al2[131072];
__device__ float   g_pool[LL * G * CC];

__device__ __forceinline__ float2 h2f(unsigned u)
{
    __half2 h = *reinterpret_cast<__half2*>(&u);
    return __half22float2(h);
}

// ---------------- kernels ----------------

__global__ void k_zero()
{
    int i = blockIdx.x * blockDim.x + threadIdx.x;   // 131072 threads
    g_deg0[i] = 0; g_fill0[i] = 0; g_scoreA[i] = 0;
    g_pack1[i] = make_float2(0.f, 0.f);
    g_pack2[i] = make_float2(0.f, 0.f);
    if (i < 65536) g_scoreB[i] = 0;
    if (i < LL * G * CC) g_pool[i] = 0.0f;
    if (i < 64) g_state0[i] = 0u;
}

__global__ void k_degree(const int* __restrict__ src, const int* __restrict__ dst, int E)
{
    for (int e = blockIdx.x * blockDim.x + threadIdx.x; e < E;
         e += gridDim.x * blockDim.x) {
        atomicAdd(&g_deg0[dst[e]], 1);
        atomicAdd(&g_scoreA[src[e]], 1);
    }
}

// exclusive scan of deg0 (decoupled lookback) + write pack0.y = rsqrt(deg+1)
__global__ void __launch_bounds__(1024, 1) k_scan()
{
    __shared__ int sh[1024];
    __shared__ int s_base;
    int tid = threadIdx.x, b = blockIdx.x;
    int gi = b * 4096 + tid * 4;
    int4 v = *(const int4*)(g_deg0 + gi);
    g_pack0[gi + 0].y = rsqrtf((float)v.x + 1.0f);
    g_pack0[gi + 1].y = rsqrtf((float)v.y + 1.0f);
    g_pack0[gi + 2].y = rsqrtf((float)v.z + 1.0f);
    g_pack0[gi + 3].y = rsqrtf((float)v.w + 1.0f);
    int tsum = v.x + v.y + v.z + v.w;
    sh[tid] = tsum;
    __syncthreads();
    int acc = tsum;
#pragma unroll
    for (int off = 1; off < 1024; off <<= 1) {
        int add = (tid >= off) ? sh[tid - off] : 0;
        __syncthreads();
        acc += add;
        sh[tid] = acc;
        __syncthreads();
    }
    int total = sh[1023];
    if (tid == 0 && b > 0)
        atomicExch(&g_state0[b], 0x40000000u | (unsigned)total);
    if (tid < 32) {
        int base = 0;
        if (b > 0) {
            int idx = b - 1 - tid;
            while (true) {
                unsigned s = 0;
                if (idx >= 0) { do { s = atomicAdd(&g_state0[idx], 0u); } while (s == 0u); }
                unsigned pm = __ballot_sync(0xffffffffu, idx >= 0 && (s & 0x80000000u));
                int firstP = pm ? (__ffs(pm) - 1) : 32;
                int c = (idx >= 0 && tid <= firstP) ? (int)(s & 0x3FFFFFFFu) : 0;
#pragma unroll
                for (int o = 16; o; o >>= 1) c += __shfl_xor_sync(0xffffffffu, c, o);
                base += c;
                if (pm) break;
                idx -= 32;
            }
        }
        if (tid == 0) {
            atomicExch(&g_state0[b], 0x80000000u | (unsigned)(base + total));
            s_base = base;
        }
    }
    __syncthreads();
    int excl = s_base + acc - tsum;
    int4 o;
    o.x = excl; o.y = excl + v.x; o.z = o.y + v.y; o.w = o.z + v.z;
    *(int4*)(g_offs0 + gi) = o;
}

__global__ void k_scatter(const int* __restrict__ src, const int* __restrict__ dst, int E)
{
    for (int e = blockIdx.x * blockDim.x + threadIdx.x; e < E;
         e += gridDim.x * blockDim.x) {
        int d = dst[e];
        int p = atomicAdd(&g_fill0[d], 1);
        g_csr0[g_offs0[d] + p] = src[e];
    }
}

// layer-0 node prep: pack0.x = ar0, al0, half copy of x
__global__ void k_nodeprep(const float* __restrict__ x,
                           const float* __restrict__ attl, const float* __restrict__ attr)
{
    int warp = (blockIdx.x * blockDim.x + threadIdx.x) >> 5;
    int lane = threadIdx.x & 31;
    float4 cv = __ldg((const float4*)(x + (size_t)warp * CC) + lane);
    float4 lv = ((const float4*)attl)[lane];
    float4 rv = ((const float4*)attr)[lane];
    float al = cv.x*lv.x + cv.y*lv.y + cv.z*lv.z + cv.w*lv.w;
    float ar = cv.x*rv.x + cv.y*rv.y + cv.z*rv.z + cv.w*rv.w;
#pragma unroll
    for (int o = 16; o; o >>= 1) {
        al += __shfl_xor_sync(0xffffffffu, al, o);
        ar += __shfl_xor_sync(0xffffffffu, ar, o);
    }
    if (lane == 0) { g_al0[warp] = al; g_pack0[warp].x = ar; }
    uint2 h;
    *reinterpret_cast<__half2*>(&h.x) = __floats2half2_rn(cv.x, cv.y);
    *reinterpret_cast<__half2*>(&h.y) = __floats2half2_rn(cv.z, cv.w);
    ((uint2*)(g_xh + (size_t)warp * CC))[lane] = h;
}

// unified aggregation: warp per dst node, masked walk of csr0, coef via pack
// (pack.y==0 encodes dropped source). All ids are orig ids.
template<int MODE>
__global__ void __launch_bounds__(256) k_agg(
                      const __half* __restrict__ feat,
                      const float2* __restrict__ pack,
                      const float* __restrict__ alC,
                      float* __restrict__ alN, float2* __restrict__ packN,
                      const float* __restrict__ attlN, const float* __restrict__ attrN,
                      __half* __restrict__ hout, int log2npg, int layer)
{
    __shared__ unsigned smax[128];
    __shared__ int2 spair[8][32];
    int tid  = threadIdx.x;
    int lane = tid & 31;
    int w    = tid >> 5;
    if (tid < 128) smax[tid] = 0;
    __syncthreads();

    int d = (blockIdx.x * blockDim.x + tid) >> 5;
    int old0;
    if (MODE == 0)      old0 = d;
    else if (MODE == 1) old0 = g_permA[d];
    else                old0 = g_permA[g_permB[d]];

    int start = g_offs0[old0];
    int cnt   = g_deg0[old0];
    float2 pkS = __ldg(&pack[old0]);
    float dind = pkS.y;
    float ald  = alC[old0];

    float4 a = {0.f, 0.f, 0.f, 0.f};
    for (int base = 0; base < cnt; base += 32) {
        int j = base + lane;
        int s0 = 0; float2 sp = make_float2(0.f, 0.f);
        if (j < cnt) {
            s0 = g_csr0[start + j];
            sp = __ldg(&pack[s0]);
        }
        bool valid = (j < cnt) && (sp.y != 0.0f);
        float coef = 0.f;
        if (valid) coef = sp.y * dind * tanhf(ald + sp.x);
        unsigned bal = __ballot_sync(0xffffffffu, valid);
        int m = __popc(bal);
        if (valid) {
            int pos = __popc(bal & ((1u << lane) - 1u));
            spair[w][pos] = make_int2(s0, __float_as_int(coef));
        }
        __syncwarp();
        int t = 0;
        for (; t + 8 <= m; t += 8) {
            uint2 p[8]; float c[8];
#pragma unroll
            for (int q = 0; q < 8; q++) {
                int2 pr = spair[w][t + q];
                c[q] = __int_as_float(pr.y);
                p[q] = __ldg((const uint2*)(feat + (size_t)pr.x * CC) + lane);
            }
#pragma unroll
            for (int q = 0; q < 8; q++) {
                float2 f0 = h2f(p[q].x), f1 = h2f(p[q].y);
                a.x += c[q]*f0.x; a.y += c[q]*f0.y;
                a.z += c[q]*f1.x; a.w += c[q]*f1.y;
            }
        }
        if (t + 4 <= m) {
            uint2 p[4]; float c[4];
#pragma unroll
            for (int q = 0; q < 4; q++) {
                int2 pr = spair[w][t + q];
                c[q] = __int_as_float(pr.y);
                p[q] = __ldg((const uint2*)(feat + (size_t)pr.x * CC) + lane);
            }
#pragma unroll
            for (int q = 0; q < 4; q++) {
                float2 f0 = h2f(p[q].x), f1 = h2f(p[q].y);
                a.x += c[q]*f0.x; a.y += c[q]*f0.y;
                a.z += c[q]*f1.x; a.w += c[q]*f1.y;
            }
            t += 4;
        }
        for (; t < m; t++) {
            int2 pr = spair[w][t];
            float cc = __int_as_float(pr.y);
            uint2 p = __ldg((const uint2*)(feat + (size_t)pr.x * CC) + lane);
            float2 f0 = h2f(p.x), f1 = h2f(p.y);
            a.x += cc*f0.x; a.y += cc*f0.y; a.z += cc*f1.x; a.w += cc*f1.y;
        }
        __syncwarp();
    }

    // self-loop + EPS*orig + relu
    uint2 pc = __ldg((const uint2*)(feat + (size_t)old0 * CC) + lane);
    uint2 po = (MODE == 0) ? pc
             : __ldg((const uint2*)(g_xh + (size_t)old0 * CC) + lane);
    float2 c01 = h2f(pc.x), c23 = h2f(pc.y);
    float2 o01 = h2f(po.x), o23 = h2f(po.y);
    float c0 = dind * dind * tanhf(ald + pkS.x);
    a.x = fmaxf(c0*c01.x + EPS_FA*o01.x + a.x, 0.f);
    a.y = fmaxf(c0*c01.y + EPS_FA*o01.y + a.y, 0.f);
    a.z = fmaxf(c0*c23.x + EPS_FA*o23.x + a.z, 0.f);
    a.w = fmaxf(c0*c23.y + EPS_FA*o23.y + a.w, 0.f);

    if (MODE < 2) {
        uint2 hh;
        *reinterpret_cast<__half2*>(&hh.x) = __floats2half2_rn(a.x, a.y);
        *reinterpret_cast<__half2*>(&hh.y) = __floats2half2_rn(a.z, a.w);
        ((uint2*)(hout + (size_t)old0 * CC))[lane] = hh;
        float4 lv = ((const float4*)attlN)[lane];
        float4 rv = ((const float4*)attrN)[lane];
        float aln = a.x*lv.x + a.y*lv.y + a.z*lv.z + a.w*lv.w;
        float arn = a.x*rv.x + a.y*rv.y + a.z*rv.z + a.w*rv.w;
#pragma unroll
        for (int o = 16; o; o >>= 1) {
            aln += __shfl_xor_sync(0xffffffffu, aln, o);
            arn += __shfl_xor_sync(0xffffffffu, arn, o);
        }
        if (lane == 0) { alN[old0] = aln; packN[old0].x = arn; }
    }

    atomicMax(&smax[lane*4 + 0], __float_as_uint(a.x));
    atomicMax(&smax[lane*4 + 1], __float_as_uint(a.y));
    atomicMax(&smax[lane*4 + 2], __float_as_uint(a.z));
    atomicMax(&smax[lane*4 + 3], __float_as_uint(a.w));
    __syncthreads();
    if (tid < 128) {
        int g = (int)((blockIdx.x * (blockDim.x >> 5)) >> log2npg);
        atomicMax((unsigned*)&g_pool[(layer * G + g) * CC + tid], smax[tid]);
    }
}

// fused exact stable top-k (counting rank), one block per graph, 1024 threads.
template<int ROUNDS>
__global__ void __launch_bounds__(1024, 1) k_rank(
                       const int* __restrict__ score, int* __restrict__ perm,
                       int* __restrict__ nmap, int kk)
{
    extern __shared__ int smem[];
    int* whist = smem;              // 32*512
    int* s_tot = smem + 32*512;     // 512
    int* s_cnt = s_tot + 512;       // 512
    int tid = threadIdx.x, w = tid >> 5, lane = tid & 31;
    int npg = ROUNDS * 1024;
    int nbase = blockIdx.x * npg + w * (ROUNDS * 32);

    for (int i = lane; i < 512; i += 32) whist[w*512 + i] = 0;
    __syncwarp();

    int seq[ROUNDS];
#pragma unroll
    for (int r = 0; r < ROUNDS; r++) {
        int i = nbase + r * 32 + lane;
        int s = min(score[i], SBINS - 1);
        unsigned mk = __match_any_sync(0xffffffffu, s);
        int intra = __popc(mk & ((1u << lane) - 1u));
        int cur = whist[w*512 + s];
        __syncwarp();
        if (intra == 0) whist[w*512 + s] = cur + __popc(mk);
        __syncwarp();
        seq[r] = cur + intra;
    }
    __syncthreads();

    if (tid < 512) {
        int run = 0;
        for (int ww = 0; ww < 32; ww++) {
            int v = whist[ww*512 + tid];
            whist[ww*512 + tid] = run;
            run += v;
        }
        s_tot[tid] = run;
        s_cnt[tid] = run;
    }
    __syncthreads();
    for (int off = 1; off < 512; off <<= 1) {
        int add = 0;
        if (tid < 512 && tid + off < 512) add = s_cnt[tid + off];
        __syncthreads();
        if (tid < 512) s_cnt[tid] += add;
        __syncthreads();
    }

#pragma unroll
    for (int r = 0; r < ROUNDS; r++) {
        int i = nbase + r * 32 + lane;
        int s = min(score[i], SBINS - 1);
        int rank = (s_cnt[s] - s_tot[s]) + whist[w*512 + s] + seq[r];
        int nm = -1;
        if (rank < kk) {
            int neu = blockIdx.x * kk + rank;
            perm[neu] = i;
            nm = neu;
        }
        nmap[i] = nm;
    }
}

// layer-1 masked degree + out-degree score + pack1.y
__global__ void k_degscore1()
{
    int j = blockIdx.x * blockDim.x + threadIdx.x;   // 0..65535
    int old0 = g_permA[j];
    int st = g_offs0[old0], c = g_deg0[old0];
    int dcur = 0;
    for (int k = 0; k < c; k++) {
        int s0 = g_csr0[st + k];
        int s1 = g_nmapA[s0];
        if (s1 >= 0) { dcur++; atomicAdd(&g_scoreB[s1], 1); }
    }
    g_pack1[old0].y = rsqrtf((float)dcur + 1.0f);
}

// layer-2 masked degree + pack2.y
__global__ void k_degscore2()
{
    int m = blockIdx.x * blockDim.x + threadIdx.x;   // 0..32767
    int old1 = g_permB[m];
    int old0 = g_permA[old1];
    int st = g_offs0[old0], c = g_deg0[old0];
    int dcur = 0;
    for (int k = 0; k < c; k++) {
        int s0 = g_csr0[st + k];
        int s1 = g_nmapA[s0];
        if (s1 >= 0 && g_nmapB[s1] >= 0) dcur++;
    }
    g_pack2[old0].y = rsqrtf((float)dcur + 1.0f);
}

// GRU (h0=0) + final linears + root residual
__global__ void k_head(const float* __restrict__ w_ih, const float* __restrict__ b_ih,
                       const float* __restrict__ b_hh,
                       const float* __restrict__ w_fin, const float* __restrict__ b_fin,
                       const float* __restrict__ w_root, const float* __restrict__ b_root,
                       const float* __restrict__ root, const float* __restrict__ alpha_p,
                       float* __restrict__ out)
{
    __shared__ float fused[LL * CC];
    __shared__ float hgru[HH];
    __shared__ float rootv[CC];
    int g = blockIdx.x, t = threadIdx.x;
    for (int i = t; i < LL * CC; i += 256) {
        int layer = i >> 7, c = i & 127;
        fused[i] = g_pool[layer * G * CC + g * CC + c];
    }
    if (t < CC) rootv[t] = root[g * CC + t];
    __syncthreads();

    float gr = b_ih[t], gz = b_ih[HH + t], gn = b_ih[2 * HH + t];
    const float* wr = w_ih + (size_t)t            * (LL * CC);
    const float* wz = w_ih + (size_t)(HH + t)     * (LL * CC);
    const float* wn = w_ih + (size_t)(2 * HH + t) * (LL * CC);
    for (int j = 0; j < LL * CC; j++) {
        float f = fused[j];
        gr += wr[j] * f; gz += wz[j] * f; gn += wn[j] * f;
    }
    float r  = 1.0f / (1.0f + expf(-(gr + b_hh[t])));
    float z  = 1.0f / (1.0f + expf(-(gz + b_hh[HH + t])));
    float nc = tanhf(gn + r * b_hh[2 * HH + t]);
    hgru[t] = (1.0f - z) * nc;
    __syncthreads();

    if (t < CC) {
        float acc = b_fin[t];
        const float* wf = w_fin + (size_t)t * HH;
        for (int j = 0; j < HH; j++) acc += wf[j] * hgru[j];
        float re = b_root[t];
        const float* wo = w_root + (size_t)t * CC;
        for (int j = 0; j < CC; j++) re += wo[j] * rootv[j];
        float a = *alpha_p;
        out[g * CC + t] = a * acc + (1.0f - a) * re;
    }
}

// ---------------- launch ----------------

extern "C" void kernel_launch(void* const* d_in, const int* in_sizes, int n_in,
                              void* d_out, int out_size)
{
    const float* x      = (const float*)d_in[0];
    const int*   ei     = (const int*)  d_in[1];
    const float* root   = (const float*)d_in[3];
    const float* att_l  = (const float*)d_in[4];
    const float* att_r  = (const float*)d_in[5];
    const float* w_ih   = (const float*)d_in[6];
    const float* b_ih   = (const float*)d_in[8];
    const float* b_hh   = (const float*)d_in[9];
    const float* w_fin  = (const float*)d_in[10];
    const float* b_fin  = (const float*)d_in[11];
    const float* w_root = (const float*)d_in[12];
    const float* b_root = (const float*)d_in[13];
    const float* alpha  = (const float*)d_in[14];
    float* out = (float*)d_out;

    int E = in_sizes[1] / 2;
    const int* src0 = ei;
    const int* dst0 = ei + E;

    __half *xh, *h0, *h1;
    int *scoreA, *scoreB, *permA, *permB, *nmapA, *nmapB;
    float2 *pack0, *pack1, *pack2;
    float *al0, *al1, *al2;
    cudaGetSymbolAddress((void**)&xh,     g_xh);
    cudaGetSymbolAddress((void**)&h0,     g_h0);
    cudaGetSymbolAddress((void**)&h1,     g_h1);
    cudaGetSymbolAddress((void**)&scoreA, g_scoreA);
    cudaGetSymbolAddress((void**)&scoreB, g_scoreB);
    cudaGetSymbolAddress((void**)&permA,  g_permA);
    cudaGetSymbolAddress((void**)&permB,  g_permB);
    cudaGetSymbolAddress((void**)&nmapA,  g_nmapA);
    cudaGetSymbolAddress((void**)&nmapB,  g_nmapB);
    cudaGetSymbolAddress((void**)&pack0,  g_pack0);
    cudaGetSymbolAddress((void**)&pack1,  g_pack1);
    cudaGetSymbolAddress((void**)&pack2,  g_pack2);
    cudaGetSymbolAddress((void**)&al0,    g_al0);
    cudaGetSymbolAddress((void**)&al1,    g_al1);
    cudaGetSymbolAddress((void**)&al2,    g_al2);

    static cudaStream_t sA = nullptr, sB = nullptr;
    static cudaEvent_t e0, eNP, eDeg, eScat, eA0, eDS1, eDS2;
    if (!sA) {
        cudaStreamCreateWithFlags(&sA, cudaStreamNonBlocking);
        cudaStreamCreateWithFlags(&sB, cudaStreamNonBlocking);
        cudaEventCreateWithFlags(&e0,    cudaEventDisableTiming);
        cudaEventCreateWithFlags(&eNP,   cudaEventDisableTiming);
        cudaEventCreateWithFlags(&eDeg,  cudaEventDisableTiming);
        cudaEventCreateWithFlags(&eScat, cudaEventDisableTiming);
        cudaEventCreateWithFlags(&eA0,   cudaEventDisableTiming);
        cudaEventCreateWithFlags(&eDS1,  cudaEventDisableTiming);
        cudaEventCreateWithFlags(&eDS2,  cudaEventDisableTiming);
        cudaFuncSetAttribute(k_rank<16>, cudaFuncAttributeMaxDynamicSharedMemorySize, 70656);
        cudaFuncSetAttribute(k_rank<8>,  cudaFuncAttributeMaxDynamicSharedMemorySize, 70656);
    }
    const int RSMEM = (32*512 + 1024) * 4;

    // ---- issue order puts agg0 sixth so ncu (-s 5 -c 1) profiles it ----
    k_zero<<<512, 256>>>();
    cudaEventRecord(e0, 0);
    cudaStreamWaitEvent(sA, e0, 0);
    k_nodeprep<<<131072 / 8, 256, 0, sA>>>(x, att_l, att_r);
    cudaEventRecord(eNP, sA);

    k_degree <<<1024, 256>>>(src0, dst0, E);
    cudaEventRecord(eDeg, 0);
    k_scan   <<<32, 1024>>>();
    k_scatter<<<1024, 256>>>(src0, dst0, E);
    cudaEventRecord(eScat, 0);

    cudaStreamWaitEvent(0, eNP, 0);
    k_agg<0><<<16384, 256>>>(xh, pack0, al0,
                             al1, pack1, att_l + CC, att_r + CC, h0, 14, 0);
    cudaEventRecord(eA0, 0);

    // side stream B (forked via eDeg): rank + masked degrees, hidden under agg0
    cudaStreamWaitEvent(sB, eDeg, 0);
    k_rank<16><<<G, 1024, RSMEM, sB>>>(scoreA, permA, nmapA, 8192);
    cudaStreamWaitEvent(sB, eScat, 0);
    k_degscore1<<<256, 256, 0, sB>>>();
    cudaEventRecord(eDS1, sB);
    k_rank<8><<<G, 1024, RSMEM, sB>>>(scoreB, permB, nmapB, 4096);
    k_degscore2<<<128, 256, 0, sB>>>();
    cudaEventRecord(eDS2, sB);

    // main: remaining aggregation chain
    cudaStreamWaitEvent(0, eDS1, 0);
    k_agg<1><<<8192, 256>>>(h0, pack1, al1,
                            al2, pack2, att_l + 2*CC, att_r + 2*CC, h1, 13, 1);
    cudaStreamWaitEvent(0, eDS2, 0);
    k_agg<2><<<4096, 256>>>(h1, pack2, al2,
                            nullptr, nullptr, nullptr, nullptr, nullptr, 12, 2);

    k_head<<<G, 256>>>(w_ih, b_ih, b_hh, w_fin, b_fin, w_root, b_root,
                       root, alpha, out);
}